// round 8
// baseline (speedup 1.0000x reference)
#include <cuda_runtime.h>
#include <cuda_bf16.h>
#include <cuda_fp16.h>
#include <cstdint>

// Problem constants
#define B_   16384
#define DIN  1024
#define D_   512
#define K_   8192
#define KP2  3072          // gemm1 packed K: [a0|a0|a1] . [b0|b1|b0]

#define MARGIN2 1.25f      // e4m3 approx-score collect margin (7 sigma + f16 slack)
#define CAP     48
#define SCL_INV 0.03125f   // 2 / (4*16)

// ---------------------------------------------------------------------------
// Scratch (device globals; allocations forbidden)
// ---------------------------------------------------------------------------
__device__ float  g_ze[(size_t)B_ * D_];     // z_e fp32
__device__ float  g_c2[K_];
__device__ float  g_zz[B_];
__device__ int    g_idx[B_];
__device__ float  g_pmin[8 * B_];            // per-(code-slice, row) partial min
__device__ __half g_dh[(size_t)B_ * K_];     // approx scores fp16, 256MB
__device__ __nv_bfloat16 g_xs[(size_t)B_ * KP2];   // packed x splits (gemm1)
__device__ __nv_bfloat16 g_ws[(size_t)D_ * KP2];   // packed W splits (gemm1)
__device__ uint8_t g_z8[(size_t)B_ * D_];    // e4m3(4*z_e)
__device__ uint8_t g_c8[(size_t)K_ * D_];    // e4m3(16*cb)

// ---------------------------------------------------------------------------
// PTX helpers (baseline PTX only: works at .target sm_100)
// ---------------------------------------------------------------------------
__device__ __forceinline__ uint32_t smem_u32(const void* p) {
    uint32_t a;
    asm("{ .reg .u64 t; cvta.to.shared.u64 t, %1; cvt.u32.u64 %0, t; }" : "=r"(a) : "l"(p));
    return a;
}
__device__ __forceinline__ void cp_async16(uint32_t saddr, const void* gaddr) {
    asm volatile("cp.async.cg.shared.global [%0], [%1], 16;" :: "r"(saddr), "l"(gaddr));
}
__device__ __forceinline__ void cp_commit() { asm volatile("cp.async.commit_group;"); }
__device__ __forceinline__ void cp_wait1()  { asm volatile("cp.async.wait_group 1;" ::: "memory"); }

__device__ __forceinline__ void ldsm_x4(uint32_t& r0, uint32_t& r1, uint32_t& r2, uint32_t& r3,
                                        uint32_t addr) {
    asm volatile("ldmatrix.sync.aligned.m8n8.x4.shared.b16 {%0,%1,%2,%3}, [%4];"
                 : "=r"(r0), "=r"(r1), "=r"(r2), "=r"(r3) : "r"(addr));
}
__device__ __forceinline__ void mma_bf16(float* c, const uint32_t* a, uint32_t b0, uint32_t b1) {
    asm volatile("mma.sync.aligned.m16n8k16.row.col.f32.bf16.bf16.f32 "
                 "{%0,%1,%2,%3}, {%4,%5,%6,%7}, {%8,%9}, {%0,%1,%2,%3};"
                 : "+f"(c[0]), "+f"(c[1]), "+f"(c[2]), "+f"(c[3])
                 : "r"(a[0]), "r"(a[1]), "r"(a[2]), "r"(a[3]), "r"(b0), "r"(b1));
}
__device__ __forceinline__ void mma_e4m3(float* c, const uint32_t* a, uint32_t b0, uint32_t b1) {
    asm volatile("mma.sync.aligned.m16n8k32.row.col.f32.e4m3.e4m3.f32 "
                 "{%0,%1,%2,%3}, {%4,%5,%6,%7}, {%8,%9}, {%0,%1,%2,%3};"
                 : "+f"(c[0]), "+f"(c[1]), "+f"(c[2]), "+f"(c[3])
                 : "r"(a[0]), "r"(a[1]), "r"(a[2]), "r"(a[3]), "r"(b0), "r"(b1));
}
// first operand -> high byte (cvt pack convention)
__device__ __forceinline__ uint16_t f2_e4m3(float hi, float lo) {
    uint16_t r;
    asm("cvt.rn.satfinite.e4m3x2.f32 %0, %1, %2;" : "=h"(r) : "f"(hi), "f"(lo));
    return r;
}

// gemm1 swizzles (bf16, 128B rows)
#define STAGEB 16384
// phase1 fp8 A-resident swizzle: 512B rows, 32 chunks
#define SWA8(r, c) ((r) * 512 + ((((c) & 24) | (((c) ^ (r)) & 7)) << 4))
// phase1 fp8 B-stage swizzle: 64B rows, 4 chunks
#define SWB8(r, c) ((r) * 64 + ((((c) ^ (((r) >> 1) & 3)) & 3) << 4))

// ---------------------------------------------------------------------------
// zz (fp64 accumulation)
// ---------------------------------------------------------------------------
__global__ void zz_kernel() {
    int row  = blockIdx.x * 8 + (threadIdx.x >> 5);
    int lane = threadIdx.x & 31;
    const float* p = g_ze + (size_t)row * D_;
    double s = 0.0;
    #pragma unroll 4
    for (int i = lane; i < D_; i += 32) { double v = (double)p[i]; s += v * v; }
    #pragma unroll
    for (int o = 16; o; o >>= 1) s += __shfl_xor_sync(0xffffffffu, s, o);
    if (lane == 0) g_zz[row] = (float)s;
}

// ---------------------------------------------------------------------------
// Codebook prep: c2 + e4m3 pack (x16), single 16MB read. 1 warp per row.
// ---------------------------------------------------------------------------
__global__ void cbprep_kernel(const float* __restrict__ cb) {
    const int row  = blockIdx.x * 8 + (threadIdx.x >> 5);
    const int lane = threadIdx.x & 31;
    const float4* src = reinterpret_cast<const float4*>(cb + (size_t)row * D_);
    uint32_t* dst = reinterpret_cast<uint32_t*>(g_c8 + (size_t)row * D_);
    float s = 0.f;
    #pragma unroll
    for (int j = 0; j < 4; j++) {
        const int i = lane + j * 32;
        float4 v = src[i];
        s += v.x * v.x + v.y * v.y + v.z * v.z + v.w * v.w;
        uint16_t p0 = f2_e4m3(v.y * 16.f, v.x * 16.f);
        uint16_t p1 = f2_e4m3(v.w * 16.f, v.z * 16.f);
        dst[i] = (uint32_t)p0 | ((uint32_t)p1 << 16);
    }
    #pragma unroll
    for (int o = 16; o; o >>= 1) s += __shfl_xor_sync(0xffffffffu, s, o);
    if (lane == 0) g_c2[row] = s;
}

// ---------------------------------------------------------------------------
// Pack kernels for gemm1 operands (bf16 3-split)
// ---------------------------------------------------------------------------
__global__ void pack_x_kernel(const float* __restrict__ x) {
    const int row = blockIdx.x, t = threadIdx.x;
    float4 v = *reinterpret_cast<const float4*>(x + (size_t)row * DIN + t * 4);
    __nv_bfloat162 h01, h23, l01, l23;
    h01.x = __float2bfloat16_rn(v.x); h01.y = __float2bfloat16_rn(v.y);
    h23.x = __float2bfloat16_rn(v.z); h23.y = __float2bfloat16_rn(v.w);
    l01.x = __float2bfloat16_rn(v.x - __bfloat162float(h01.x));
    l01.y = __float2bfloat16_rn(v.y - __bfloat162float(h01.y));
    l23.x = __float2bfloat16_rn(v.z - __bfloat162float(h23.x));
    l23.y = __float2bfloat16_rn(v.w - __bfloat162float(h23.y));
    __nv_bfloat162* d = reinterpret_cast<__nv_bfloat162*>(g_xs + (size_t)row * KP2 + t * 4);
    d[0] = h01; d[1] = h23;
    d += 512;  d[0] = h01; d[1] = h23;
    d += 512;  d[0] = l01; d[1] = l23;
}

__global__ void pack_w_kernel(const float* __restrict__ w) {
    const int row = blockIdx.x, t = threadIdx.x;
    float4 v = *reinterpret_cast<const float4*>(w + (size_t)row * DIN + t * 4);
    __nv_bfloat162 h01, h23, l01, l23;
    h01.x = __float2bfloat16_rn(v.x); h01.y = __float2bfloat16_rn(v.y);
    h23.x = __float2bfloat16_rn(v.z); h23.y = __float2bfloat16_rn(v.w);
    l01.x = __float2bfloat16_rn(v.x - __bfloat162float(h01.x));
    l01.y = __float2bfloat16_rn(v.y - __bfloat162float(h01.y));
    l23.x = __float2bfloat16_rn(v.z - __bfloat162float(h23.x));
    l23.y = __float2bfloat16_rn(v.w - __bfloat162float(h23.y));
    __nv_bfloat162* d = reinterpret_cast<__nv_bfloat162*>(g_ws + (size_t)row * KP2 + t * 4);
    d[0] = h01; d[1] = h23;
    d += 512;  d[0] = l01; d[1] = l23;
    d += 512;  d[0] = h01; d[1] = h23;
}

// ---------------------------------------------------------------------------
// GEMM1 via mma.sync: z_e = x @ W^T with packed 3-split (K''=3072).
// Epilogue emits fp32 z_e AND e4m3(4*z_e).
// ---------------------------------------------------------------------------
#define NS1    3
#define BLKK   64
#define SM1_B  (NS1 * STAGEB)
#define SM1TOT (2 * NS1 * STAGEB)   // 96KB

__global__ __launch_bounds__(256, 1) void gemm1_mma_kernel() {
    extern __shared__ char sm[];
    const uint32_t sbase = smem_u32(sm);
    const int tid  = threadIdx.x;
    const int lane = tid & 31;
    const int wid  = tid >> 5;
    const int warp_m = wid & 1;
    const int warp_n = wid >> 1;
    const int row0 = blockIdx.y * 128;
    const int col0 = blockIdx.x * 128;
    const int NKIT = KP2 / BLKK;      // 48

    const __nv_bfloat16* gA = g_xs + (size_t)row0 * KP2;
    const __nv_bfloat16* gB = g_ws + (size_t)col0 * KP2;

    float acc[4][4][4];
    #pragma unroll
    for (int mf = 0; mf < 4; mf++)
        #pragma unroll
        for (int nf = 0; nf < 4; nf++)
            #pragma unroll
            for (int q = 0; q < 4; q++) acc[mf][nf][q] = 0.f;

    #define G1_ISSUE(stg, kit) do {                                                \
        const uint32_t As_ = sbase + (stg) * STAGEB;                               \
        const uint32_t Bs_ = sbase + SM1_B + (stg) * STAGEB;                       \
        const int koff_ = (kit) * BLKK;                                            \
        _Pragma("unroll")                                                          \
        for (int i_ = 0; i_ < 4; i_++) {                                           \
            int id_ = tid + i_ * 256;                                              \
            int r_  = id_ >> 3;                                                    \
            int c_  = id_ & 7;                                                     \
            int cp_ = c_ ^ (r_ & 7);                                               \
            cp_async16(As_ + r_ * 128 + cp_ * 16, gA + (size_t)r_ * KP2 + koff_ + c_ * 8); \
            cp_async16(Bs_ + r_ * 128 + cp_ * 16, gB + (size_t)r_ * KP2 + koff_ + c_ * 8); \
        }                                                                          \
    } while (0)

    G1_ISSUE(0, 0); cp_commit();
    G1_ISSUE(1, 1); cp_commit();

    const int g = lane >> 3;
    const int r8 = lane & 7;

    for (int kit = 0; kit < NKIT; kit++) {
        cp_wait1();
        __syncthreads();
        if (kit + 2 < NKIT) G1_ISSUE((kit + 2) % NS1, kit + 2);
        cp_commit();

        const int stg = kit % NS1;
        const uint32_t Abase = sbase + stg * STAGEB;
        const uint32_t Bbase = sbase + SM1_B + stg * STAGEB;

        #pragma unroll
        for (int ks = 0; ks < 4; ks++) {
            uint32_t afr[4][4];
            #pragma unroll
            for (int mf = 0; mf < 4; mf++) {
                int rr = warp_m * 64 + mf * 16 + ((g & 1) << 3) + r8;
                int ch = 2 * ks + (g >> 1);
                ldsm_x4(afr[mf][0], afr[mf][1], afr[mf][2], afr[mf][3],
                        Abase + rr * 128 + ((ch ^ (rr & 7)) << 4));
            }
            uint32_t bfr[2][4];
            #pragma unroll
            for (int nf2 = 0; nf2 < 2; nf2++) {
                int rr = warp_n * 32 + nf2 * 16 + ((g >> 1) << 3) + r8;
                int ch = 2 * ks + (g & 1);
                ldsm_x4(bfr[nf2][0], bfr[nf2][1], bfr[nf2][2], bfr[nf2][3],
                        Bbase + rr * 128 + ((ch ^ (rr & 7)) << 4));
            }
            #pragma unroll
            for (int mf = 0; mf < 4; mf++)
                #pragma unroll
                for (int nf = 0; nf < 4; nf++)
                    mma_bf16(acc[mf][nf], afr[mf],
                             bfr[nf >> 1][(nf & 1) * 2], bfr[nf >> 1][(nf & 1) * 2 + 1]);
        }
    }
    #undef G1_ISSUE

    #pragma unroll
    for (int mf = 0; mf < 4; mf++)
        #pragma unroll
        for (int h = 0; h < 2; h++) {
            const int row = row0 + warp_m * 64 + mf * 16 + h * 8 + (lane >> 2);
            #pragma unroll
            for (int nf = 0; nf < 4; nf++) {
                const int col = col0 + warp_n * 32 + nf * 8 + (lane & 3) * 2;
                float2 o; o.x = acc[mf][nf][h * 2]; o.y = acc[mf][nf][h * 2 + 1];
                *reinterpret_cast<float2*>(g_ze + (size_t)row * D_ + col) = o;
                *reinterpret_cast<uint16_t*>(g_z8 + (size_t)row * D_ + col) =
                    f2_e4m3(o.y * 4.f, o.x * 4.f);
            }
        }
}

// ---------------------------------------------------------------------------
// Phase 1: e4m3 approx GEMM (m16n8k32, 2x bf16 rate). Stores fp16 scores
// s = c2 - 0.03125*dot to g_dh + branchless running min -> g_pmin.
// A resident (64KB swizzled), B streamed 8KB x 3 stages. grid (8, 128).
// ---------------------------------------------------------------------------
#define P1_SM_A  0
#define P1_SM_B  65536
#define STG8     8192
#define P1_SMTOT (65536 + 3 * STG8)   // 90112

__global__ __launch_bounds__(256, 1) void phase1_kernel() {
    extern __shared__ char sm[];
    const uint32_t sbase = smem_u32(sm);
    const int tid  = threadIdx.x;
    const int lane = tid & 31;
    const int wid  = tid >> 5;
    const int warp_m = wid & 1;
    const int warp_n = wid >> 1;
    const int row0 = blockIdx.y * 128;
    const int code_base = blockIdx.x * 1024;

    // resident A: 128 rows x 32 chunks(16B) of fp8
    {
        const uint8_t* gA = g_z8 + (size_t)row0 * D_;
        #pragma unroll
        for (int i = 0; i < 16; i++) {
            int idx = tid + i * 256;
            int r   = idx >> 5;
            int c16 = idx & 31;
            cp_async16(sbase + P1_SM_A + SWA8(r, c16), gA + (size_t)r * D_ + c16 * 16);
        }
    }
    cp_commit();

    #define P1_ISSUE(stg, u) do {                                                  \
        const uint32_t Bs_ = sbase + P1_SM_B + (stg) * STG8;                       \
        const int nt_ = (u) >> 3, kit_ = (u) & 7;                                  \
        const uint8_t* gB_ = g_c8 + (size_t)(code_base + nt_ * 128) * D_;          \
        _Pragma("unroll")                                                          \
        for (int i_ = 0; i_ < 2; i_++) {                                           \
            int id_ = tid + i_ * 256;                                              \
            int r_  = id_ >> 2;                                                    \
            int c_  = id_ & 3;                                                     \
            cp_async16(Bs_ + SWB8(r_, c_), gB_ + (size_t)r_ * D_ + kit_ * 64 + c_ * 16); \
        }                                                                          \
    } while (0)

    P1_ISSUE(0, 0); cp_commit();
    P1_ISSUE(1, 1); cp_commit();

    const int g = lane >> 3;
    const int r8 = lane & 7;
    float acc[4][4][4];
    float rmin[8];
    #pragma unroll
    for (int i = 0; i < 8; i++) rmin[i] = 3.4e38f;

    for (int u = 0; u < 64; u++) {
        const int nt = u >> 3, kit = u & 7;
        cp_wait1();
        __syncthreads();
        if (u + 2 < 64) P1_ISSUE((u + 2) % 3, u + 2);
        cp_commit();

        if (kit == 0) {
            #pragma unroll
            for (int mf = 0; mf < 4; mf++)
                #pragma unroll
                for (int nf = 0; nf < 4; nf++)
                    #pragma unroll
                    for (int q = 0; q < 4; q++) acc[mf][nf][q] = 0.f;
        }

        const uint32_t Bbase = sbase + P1_SM_B + (u % 3) * STG8;
        // kit = 64 bytes of K = 2 x k32 mma steps
        #pragma unroll
        for (int ks = 0; ks < 2; ks++) {
            uint32_t afr[4][4];
            #pragma unroll
            for (int mf = 0; mf < 4; mf++) {
                int rr  = warp_m * 64 + mf * 16 + ((g & 1) << 3) + r8;
                int c16 = kit * 4 + 2 * ks + (g >> 1);
                ldsm_x4(afr[mf][0], afr[mf][1], afr[mf][2], afr[mf][3],
                        sbase + P1_SM_A + SWA8(rr, c16));
            }
            uint32_t bfr[2][4];
            #pragma unroll
            for (int nf2 = 0; nf2 < 2; nf2++) {
                int rr = warp_n * 32 + nf2 * 16 + ((g >> 1) << 3) + r8;
                int ch = 2 * ks + (g & 1);
                ldsm_x4(bfr[nf2][0], bfr[nf2][1], bfr[nf2][2], bfr[nf2][3],
                        Bbase + SWB8(rr, ch));
            }
            #pragma unroll
            for (int mf = 0; mf < 4; mf++)
                #pragma unroll
                for (int nf = 0; nf < 4; nf++)
                    mma_e4m3(acc[mf][nf], afr[mf],
                             bfr[nf >> 1][(nf & 1) * 2], bfr[nf >> 1][(nf & 1) * 2 + 1]);
        }

        if (kit == 7) {   // tile done: store f16 scores + fold min (branchless)
            #pragma unroll
            for (int nf = 0; nf < 4; nf++) {
                const int code0 = code_base + nt * 128 + warp_n * 32 + nf * 8 + (lane & 3) * 2;
                const float c2a = __ldg(&g_c2[code0]);
                const float c2b = __ldg(&g_c2[code0 + 1]);
                #pragma unroll
                for (int mf = 0; mf < 4; mf++)
                    #pragma unroll
                    for (int h = 0; h < 2; h++) {
                        const int ridx = mf * 2 + h;
                        const int row = row0 + warp_m * 64 + mf * 16 + h * 8 + (lane >> 2);
                        float v0 = c2a - SCL_INV * acc[mf][nf][h * 2 + 0];
                        float v1 = c2b - SCL_INV * acc[mf][nf][h * 2 + 1];
                        rmin[ridx] = fminf(rmin[ridx], fminf(v0, v1));
                        *reinterpret_cast<__half2*>(g_dh + (size_t)row * K_ + code0) =
                            __floats2half2_rn(v0, v1);
                    }
            }
        }
    }
    #undef P1_ISSUE

    // block reduce per-row mins (16 owners per row) -> g_pmin[bx][row]
    __syncthreads();
    float* rv = reinterpret_cast<float*>(sm + P1_SM_B);   // [128][16] = 8KB
    const int slot = warp_n * 4 + (lane & 3);
    #pragma unroll
    for (int ridx = 0; ridx < 8; ridx++) {
        const int mf = ridx >> 1, h = ridx & 1;
        const int rl = warp_m * 64 + mf * 16 + h * 8 + (lane >> 2);
        rv[rl * 16 + slot] = rmin[ridx];
    }
    __syncthreads();
    if (tid < 128) {
        float m = rv[tid * 16];
        #pragma unroll
        for (int j = 1; j < 16; j++) m = fminf(m, rv[tid * 16 + j]);
        g_pmin[blockIdx.x * B_ + row0 + tid] = m;
    }
}

// ---------------------------------------------------------------------------
// Phase 2: gmin from g_pmin, one sweep of fp16 scores, exact fp64 rescore
// with reference-grid fp32 rounding + index tie-break. 1 warp per row.
// ---------------------------------------------------------------------------
__global__ __launch_bounds__(256) void phase2_kernel(const float* __restrict__ cb) {
    __shared__ int s_cnt[8];
    __shared__ int s_list[8][CAP];
    const int wid  = threadIdx.x >> 5;
    const int lane = threadIdx.x & 31;
    const int row  = blockIdx.x * 8 + wid;

    float gmin = 3.4e38f;
    if (lane < 8) gmin = g_pmin[lane * B_ + row];
    #pragma unroll
    for (int o = 4; o; o >>= 1) gmin = fminf(gmin, __shfl_xor_sync(0xffffffffu, gmin, o));
    gmin = __shfl_sync(0xffffffffu, gmin, 0);
    const float thr = gmin + MARGIN2;

    if (lane == 0) s_cnt[wid] = 0;
    __syncwarp();

    const uint4* dp = reinterpret_cast<const uint4*>(g_dh + (size_t)row * K_);
    #pragma unroll 4
    for (int i = 0; i < 32; i++) {
        uint4 v = dp[lane + i * 32];
        const int k0 = (lane + i * 32) * 8;
        const uint32_t w[4] = { v.x, v.y, v.z, v.w };
        #pragma unroll
        for (int q = 0; q < 4; q++) {
            __half2 h = *reinterpret_cast<const __half2*>(&w[q]);
            float2 f = __half22float2(h);
            if (f.x < thr) { int p = atomicAdd(&s_cnt[wid], 1); if (p < CAP) s_list[wid][p] = k0 + q * 2; }
            if (f.y < thr) { int p = atomicAdd(&s_cnt[wid], 1); if (p < CAP) s_list[wid][p] = k0 + q * 2 + 1; }
        }
    }
    __syncwarp();
    const int ncand = s_cnt[wid];

    const float* ze = g_ze + (size_t)row * D_;
    const float  zz = g_zz[row];
    float bv = 3.4e38f;
    int   bi = 0x7fffffff;

    if (ncand <= CAP) {
        for (int c = 0; c < ncand; c++) {
            const int k = s_list[wid][c];
            const float* cr = cb + (size_t)k * D_;
            double d = 0.0;
            #pragma unroll
            for (int j = 0; j < 16; j++) {
                int dd = lane + j * 32;
                d = fma((double)ze[dd], (double)cr[dd], d);
            }
            #pragma unroll
            for (int o = 16; o; o >>= 1) d += __shfl_xor_sync(0xffffffffu, d, o);
            float t = __fadd_rn(zz, -2.0f * (float)d);
            float v = __fadd_rn(t, g_c2[k]);
            if (v < bv || (v == bv && k < bi)) { bv = v; bi = k; }
        }
    } else {
        for (int k = 0; k < K_; k++) {
            const float* cr = cb + (size_t)k * D_;
            double d = 0.0;
            #pragma unroll
            for (int j = 0; j < 16; j++) {
                int dd = lane + j * 32;
                d = fma((double)ze[dd], (double)cr[dd], d);
            }
            #pragma unroll
            for (int o = 16; o; o >>= 1) d += __shfl_xor_sync(0xffffffffu, d, o);
            float t = __fadd_rn(zz, -2.0f * (float)d);
            float v = __fadd_rn(t, g_c2[k]);
            if (v < bv || (v == bv && k < bi)) { bv = v; bi = k; }
        }
    }
    if (lane == 0) g_idx[row] = bi;
}

// ---------------------------------------------------------------------------
// Output assembly
// ---------------------------------------------------------------------------
__global__ void output_kernel(const float* __restrict__ cb, float* __restrict__ out) {
    const int b   = blockIdx.x;
    const int tid = threadIdx.x;
    const int idx = g_idx[b];

    const float* ze = g_ze + (size_t)b * D_;
    const float* zq = cb   + (size_t)idx * D_;
    float*       o  = out  + (size_t)b * D_;

    float s = 0.f;
    #pragma unroll
    for (int d = tid; d < D_; d += 128) {
        float e    = ze[d];
        float q    = zq[d];
        float diff = q - e;
        o[d] = e + diff;
        s += diff * diff;
    }
    __shared__ float red[128];
    red[tid] = s;
    __syncthreads();
    #pragma unroll
    for (int o2 = 64; o2; o2 >>= 1) {
        if (tid < o2) red[tid] += red[tid + o2];
        __syncthreads();
    }
    if (tid == 0) {
        out[(size_t)B_ * D_ + b]      = (float)idx;
        out[(size_t)B_ * D_ + B_ + b] = red[0] / (float)D_;
    }
}

// ---------------------------------------------------------------------------
extern "C" void kernel_launch(void* const* d_in, const int* in_sizes, int n_in,
                              void* d_out, int out_size) {
    const float* x  = (const float*)d_in[0];
    const float* W  = (const float*)d_in[1];
    const float* cb = (const float*)d_in[2];
    float* out = (float*)d_out;
    (void)in_sizes; (void)n_in; (void)out_size;

    cudaFuncSetAttribute(gemm1_mma_kernel, cudaFuncAttributeMaxDynamicSharedMemorySize, SM1TOT);
    cudaFuncSetAttribute(phase1_kernel,    cudaFuncAttributeMaxDynamicSharedMemorySize, P1_SMTOT);

    pack_x_kernel<<<B_, 256>>>(x);
    pack_w_kernel<<<D_, 256>>>(W);
    cbprep_kernel<<<K_ / 8, 256>>>(cb);
    gemm1_mma_kernel<<<dim3(4, 128), 256, SM1TOT>>>();
    zz_kernel<<<B_ / 8, 256>>>();
    phase1_kernel<<<dim3(8, 128), 256, P1_SMTOT>>>();
    phase2_kernel<<<B_ / 8, 256>>>(cb);
    output_kernel<<<B_, 128>>>(cb, out);
}

// round 9
// speedup vs baseline: 1.1502x; 1.1502x over previous
#include <cuda_runtime.h>
#include <cuda_bf16.h>
#include <cuda_fp16.h>
#include <cstdint>

// Problem constants
#define B_   16384
#define DIN  1024
#define D_   512
#define K_   8192
#define KP2  3072          // gemm1 packed K: [a0|a0|a1] . [b0|b1|b0]

#define MARGIN2 0.08f      // collect margin incl. f16 quantization slack
#define CAP     32

// ---------------------------------------------------------------------------
// Scratch (device globals; allocations forbidden)
// ---------------------------------------------------------------------------
__device__ float  g_ze[(size_t)B_ * D_];     // z_e fp32
__device__ float  g_c2[K_];
__device__ float  g_zz[B_];
__device__ int    g_idx[B_];
__device__ float  g_pmin[8 * B_];            // per-(code-slice, row) partial min
__device__ __half g_dh[(size_t)B_ * K_];     // approx scores fp16, 256MB
__device__ __nv_bfloat16 g_xs[(size_t)B_ * KP2];   // packed x splits
__device__ __nv_bfloat16 g_ws[(size_t)D_ * KP2];   // packed W splits
__device__ __nv_bfloat16 g_zb[(size_t)B_ * D_];    // bf16(z_e)
__device__ __nv_bfloat16 g_cbb[(size_t)K_ * D_];   // bf16(cb)

// ---------------------------------------------------------------------------
// PTX helpers (baseline PTX only: works at .target sm_100)
// ---------------------------------------------------------------------------
__device__ __forceinline__ uint32_t smem_u32(const void* p) {
    uint32_t a;
    asm("{ .reg .u64 t; cvta.to.shared.u64 t, %1; cvt.u32.u64 %0, t; }" : "=r"(a) : "l"(p));
    return a;
}
__device__ __forceinline__ void cp_async16(uint32_t saddr, const void* gaddr) {
    asm volatile("cp.async.cg.shared.global [%0], [%1], 16;" :: "r"(saddr), "l"(gaddr));
}
__device__ __forceinline__ void cp_commit() { asm volatile("cp.async.commit_group;"); }
__device__ __forceinline__ void cp_wait1()  { asm volatile("cp.async.wait_group 1;" ::: "memory"); }

__device__ __forceinline__ void ldsm_x4(uint32_t& r0, uint32_t& r1, uint32_t& r2, uint32_t& r3,
                                        uint32_t addr) {
    asm volatile("ldmatrix.sync.aligned.m8n8.x4.shared.b16 {%0,%1,%2,%3}, [%4];"
                 : "=r"(r0), "=r"(r1), "=r"(r2), "=r"(r3) : "r"(addr));
}
__device__ __forceinline__ void mma_bf16(float* c, const uint32_t* a, uint32_t b0, uint32_t b1) {
    asm volatile("mma.sync.aligned.m16n8k16.row.col.f32.bf16.bf16.f32 "
                 "{%0,%1,%2,%3}, {%4,%5,%6,%7}, {%8,%9}, {%0,%1,%2,%3};"
                 : "+f"(c[0]), "+f"(c[1]), "+f"(c[2]), "+f"(c[3])
                 : "r"(a[0]), "r"(a[1]), "r"(a[2]), "r"(a[3]), "r"(b0), "r"(b1));
}

// Swizzles:
// A-resident (phase1): 1024B rows, 64 x 16B chunks, XOR within 8-chunk groups
#define SWA(r, c) ((r) * 1024 + ((((c) & 0x38) | (((c) & 7) ^ ((r) & 7))) << 4))
// K=128 bf16 stage tiles: 256B rows, 16 x 16B chunks, XOR within 8-chunk groups
#define SWK128(r, c) ((r) * 256 + ((((c) & 8) | (((c) ^ (r)) & 7)) << 4))

// ---------------------------------------------------------------------------
// zz (fp64 accumulation)
// ---------------------------------------------------------------------------
__global__ void zz_kernel() {
    int row  = blockIdx.x * 8 + (threadIdx.x >> 5);
    int lane = threadIdx.x & 31;
    const float* p = g_ze + (size_t)row * D_;
    double s = 0.0;
    #pragma unroll 4
    for (int i = lane; i < D_; i += 32) { double v = (double)p[i]; s += v * v; }
    #pragma unroll
    for (int o = 16; o; o >>= 1) s += __shfl_xor_sync(0xffffffffu, s, o);
    if (lane == 0) g_zz[row] = (float)s;
}

// ---------------------------------------------------------------------------
// Codebook prep: c2 + bf16 pack, single 16MB read. 1 warp per code row.
// ---------------------------------------------------------------------------
__global__ void cbprep_kernel(const float* __restrict__ cb) {
    const int row  = blockIdx.x * 8 + (threadIdx.x >> 5);
    const int lane = threadIdx.x & 31;
    const float4* src = reinterpret_cast<const float4*>(cb + (size_t)row * D_);
    __nv_bfloat162* dst = reinterpret_cast<__nv_bfloat162*>(g_cbb + (size_t)row * D_);
    float s = 0.f;
    #pragma unroll
    for (int j = 0; j < 4; j++) {
        const int i = lane + j * 32;
        float4 v = src[i];
        s += v.x * v.x + v.y * v.y + v.z * v.z + v.w * v.w;
        __nv_bfloat162 h0, h1;
        h0.x = __float2bfloat16_rn(v.x); h0.y = __float2bfloat16_rn(v.y);
        h1.x = __float2bfloat16_rn(v.z); h1.y = __float2bfloat16_rn(v.w);
        dst[i * 2]     = h0;
        dst[i * 2 + 1] = h1;
    }
    #pragma unroll
    for (int o = 16; o; o >>= 1) s += __shfl_xor_sync(0xffffffffu, s, o);
    if (lane == 0) g_c2[row] = s;
}

// ---------------------------------------------------------------------------
// Pack kernels for gemm1 operands (bf16 3-split)
// ---------------------------------------------------------------------------
__global__ void pack_x_kernel(const float* __restrict__ x) {
    const int row = blockIdx.x, t = threadIdx.x;
    float4 v = *reinterpret_cast<const float4*>(x + (size_t)row * DIN + t * 4);
    __nv_bfloat162 h01, h23, l01, l23;
    h01.x = __float2bfloat16_rn(v.x); h01.y = __float2bfloat16_rn(v.y);
    h23.x = __float2bfloat16_rn(v.z); h23.y = __float2bfloat16_rn(v.w);
    l01.x = __float2bfloat16_rn(v.x - __bfloat162float(h01.x));
    l01.y = __float2bfloat16_rn(v.y - __bfloat162float(h01.y));
    l23.x = __float2bfloat16_rn(v.z - __bfloat162float(h23.x));
    l23.y = __float2bfloat16_rn(v.w - __bfloat162float(h23.y));
    __nv_bfloat162* d = reinterpret_cast<__nv_bfloat162*>(g_xs + (size_t)row * KP2 + t * 4);
    d[0] = h01; d[1] = h23;
    d += 512;  d[0] = h01; d[1] = h23;
    d += 512;  d[0] = l01; d[1] = l23;
}

__global__ void pack_w_kernel(const float* __restrict__ w) {
    const int row = blockIdx.x, t = threadIdx.x;
    float4 v = *reinterpret_cast<const float4*>(w + (size_t)row * DIN + t * 4);
    __nv_bfloat162 h01, h23, l01, l23;
    h01.x = __float2bfloat16_rn(v.x); h01.y = __float2bfloat16_rn(v.y);
    h23.x = __float2bfloat16_rn(v.z); h23.y = __float2bfloat16_rn(v.w);
    l01.x = __float2bfloat16_rn(v.x - __bfloat162float(h01.x));
    l01.y = __float2bfloat16_rn(v.y - __bfloat162float(h01.y));
    l23.x = __float2bfloat16_rn(v.z - __bfloat162float(h23.x));
    l23.y = __float2bfloat16_rn(v.w - __bfloat162float(h23.y));
    __nv_bfloat162* d = reinterpret_cast<__nv_bfloat162*>(g_ws + (size_t)row * KP2 + t * 4);
    d[0] = h01; d[1] = h23;
    d += 512;  d[0] = l01; d[1] = l23;
    d += 512;  d[0] = h01; d[1] = h23;
}

// ---------------------------------------------------------------------------
// GEMM1 via mma.sync: z_e = x @ W^T with packed 3-split (K''=3072).
// BLK_K=128 (32KB stages), 3-stage cp.async. Epilogue also emits bf16(z_e).
// ---------------------------------------------------------------------------
#define STG2   32768
#define SM1_B  (3 * STG2)
#define SM1TOT (6 * STG2)   // 192KB

__global__ __launch_bounds__(256, 1) void gemm1_mma_kernel() {
    extern __shared__ char sm[];
    const uint32_t sbase = smem_u32(sm);
    const int tid  = threadIdx.x;
    const int lane = tid & 31;
    const int wid  = tid >> 5;
    const int warp_m = wid & 1;
    const int warp_n = wid >> 1;
    const int row0 = blockIdx.y * 128;
    const int col0 = blockIdx.x * 128;
    const int NKIT = KP2 / 128;      // 24

    const __nv_bfloat16* gA = g_xs + (size_t)row0 * KP2;
    const __nv_bfloat16* gB = g_ws + (size_t)col0 * KP2;

    float acc[4][4][4];
    #pragma unroll
    for (int mf = 0; mf < 4; mf++)
        #pragma unroll
        for (int nf = 0; nf < 4; nf++)
            #pragma unroll
            for (int q = 0; q < 4; q++) acc[mf][nf][q] = 0.f;

    #define G1_ISSUE(stg, kit) do {                                                \
        const uint32_t As_ = sbase + (stg) * STG2;                                 \
        const uint32_t Bs_ = sbase + SM1_B + (stg) * STG2;                         \
        const int koff_ = (kit) * 128;                                             \
        _Pragma("unroll")                                                          \
        for (int i_ = 0; i_ < 8; i_++) {                                           \
            int id_ = tid + i_ * 256;                                              \
            int r_  = id_ >> 4;                                                    \
            int c_  = id_ & 15;                                                    \
            cp_async16(As_ + SWK128(r_, c_), gA + (size_t)r_ * KP2 + koff_ + c_ * 8); \
            cp_async16(Bs_ + SWK128(r_, c_), gB + (size_t)r_ * KP2 + koff_ + c_ * 8); \
        }                                                                          \
    } while (0)

    G1_ISSUE(0, 0); cp_commit();
    G1_ISSUE(1, 1); cp_commit();

    const int g = lane >> 3;
    const int r8 = lane & 7;

    for (int kit = 0; kit < NKIT; kit++) {
        cp_wait1();
        __syncthreads();
        if (kit + 2 < NKIT) G1_ISSUE((kit + 2) % 3, kit + 2);
        cp_commit();

        const int stg = kit % 3;
        const uint32_t Abase = sbase + stg * STG2;
        const uint32_t Bbase = sbase + SM1_B + stg * STG2;

        #pragma unroll
        for (int ks = 0; ks < 8; ks++) {
            uint32_t afr[4][4];
            #pragma unroll
            for (int mf = 0; mf < 4; mf++) {
                int rr = warp_m * 64 + mf * 16 + ((g & 1) << 3) + r8;
                int ch = 2 * ks + (g >> 1);
                ldsm_x4(afr[mf][0], afr[mf][1], afr[mf][2], afr[mf][3],
                        Abase + SWK128(rr, ch));
            }
            uint32_t bfr[2][4];
            #pragma unroll
            for (int nf2 = 0; nf2 < 2; nf2++) {
                int rr = warp_n * 32 + nf2 * 16 + ((g >> 1) << 3) + r8;
                int ch = 2 * ks + (g & 1);
                ldsm_x4(bfr[nf2][0], bfr[nf2][1], bfr[nf2][2], bfr[nf2][3],
                        Bbase + SWK128(rr, ch));
            }
            #pragma unroll
            for (int mf = 0; mf < 4; mf++)
                #pragma unroll
                for (int nf = 0; nf < 4; nf++)
                    mma_bf16(acc[mf][nf], afr[mf],
                             bfr[nf >> 1][(nf & 1) * 2], bfr[nf >> 1][(nf & 1) * 2 + 1]);
        }
    }
    #undef G1_ISSUE

    #pragma unroll
    for (int mf = 0; mf < 4; mf++)
        #pragma unroll
        for (int h = 0; h < 2; h++) {
            const int row = row0 + warp_m * 64 + mf * 16 + h * 8 + (lane >> 2);
            #pragma unroll
            for (int nf = 0; nf < 4; nf++) {
                const int col = col0 + warp_n * 32 + nf * 8 + (lane & 3) * 2;
                float2 o; o.x = acc[mf][nf][h * 2]; o.y = acc[mf][nf][h * 2 + 1];
                *reinterpret_cast<float2*>(g_ze + (size_t)row * D_ + col) = o;
                __nv_bfloat162 hb;
                hb.x = __float2bfloat16_rn(o.x); hb.y = __float2bfloat16_rn(o.y);
                *reinterpret_cast<__nv_bfloat162*>(g_zb + (size_t)row * D_ + col) = hb;
            }
        }
}

// ---------------------------------------------------------------------------
// Phase 1: single-pass bf16 approx GEMM, BLK_K=128 (32KB B stages).
// Stores fp16 scores s = c2 - 2*dot to g_dh + branchless running min
// -> g_pmin. A resident (128KB swizzled), B streamed 3-stage. grid (8, 128).
// ---------------------------------------------------------------------------
#define P1_SM_A  0
#define P1_SM_B  131072
#define P1_SMTOT (131072 + 3 * STG2)   // 229376 <= 232448 limit

__global__ __launch_bounds__(256, 1) void phase1_kernel() {
    extern __shared__ char sm[];
    const uint32_t sbase = smem_u32(sm);
    const int tid  = threadIdx.x;
    const int lane = tid & 31;
    const int wid  = tid >> 5;
    const int warp_m = wid & 1;
    const int warp_n = wid >> 1;
    const int row0 = blockIdx.y * 128;
    const int code_base = blockIdx.x * 1024;

    // resident A: 128 rows x 64 chunks(16B)
    {
        const __nv_bfloat16* gA = g_zb + (size_t)row0 * D_;
        #pragma unroll
        for (int i = 0; i < 32; i++) {
            int idx = tid + i * 256;
            int r   = idx >> 6;
            int c16 = idx & 63;
            cp_async16(sbase + P1_SM_A + SWA(r, c16), gA + (size_t)r * D_ + c16 * 8);
        }
    }
    cp_commit();

    #define P1_ISSUE(stg, u) do {                                                  \
        const uint32_t Bs_ = sbase + P1_SM_B + (stg) * STG2;                       \
        const int nt_ = (u) >> 2, kit_ = (u) & 3;                                  \
        const __nv_bfloat16* gB_ = g_cbb + (size_t)(code_base + nt_ * 128) * D_;   \
        _Pragma("unroll")                                                          \
        for (int i_ = 0; i_ < 8; i_++) {                                           \
            int id_ = tid + i_ * 256;                                              \
            int r_  = id_ >> 4;                                                    \
            int c_  = id_ & 15;                                                    \
            cp_async16(Bs_ + SWK128(r_, c_),                                       \
                       gB_ + (size_t)r_ * D_ + kit_ * 128 + c_ * 8);               \
        }                                                                          \
    } while (0)

    P1_ISSUE(0, 0); cp_commit();
    P1_ISSUE(1, 1); cp_commit();

    const int g = lane >> 3;
    const int r8 = lane & 7;
    float acc[4][4][4];
    float rmin[8];
    #pragma unroll
    for (int i = 0; i < 8; i++) rmin[i] = 3.4e38f;

    for (int u = 0; u < 32; u++) {
        const int nt = u >> 2, kit = u & 3;
        cp_wait1();
        __syncthreads();
        if (u + 2 < 32) P1_ISSUE((u + 2) % 3, u + 2);
        cp_commit();

        if (kit == 0) {
            #pragma unroll
            for (int mf = 0; mf < 4; mf++)
                #pragma unroll
                for (int nf = 0; nf < 4; nf++)
                    #pragma unroll
                    for (int q = 0; q < 4; q++) acc[mf][nf][q] = 0.f;
        }

        const uint32_t Bbase = sbase + P1_SM_B + (u % 3) * STG2;
        #pragma unroll
        for (int ks = 0; ks < 8; ks++) {
            uint32_t afr[4][4];
            #pragma unroll
            for (int mf = 0; mf < 4; mf++) {
                int rr  = warp_m * 64 + mf * 16 + ((g & 1) << 3) + r8;
                int c16 = kit * 16 + 2 * ks + (g >> 1);
                ldsm_x4(afr[mf][0], afr[mf][1], afr[mf][2], afr[mf][3],
                        sbase + P1_SM_A + SWA(rr, c16));
            }
            uint32_t bfr[2][4];
            #pragma unroll
            for (int nf2 = 0; nf2 < 2; nf2++) {
                int rr = warp_n * 32 + nf2 * 16 + ((g >> 1) << 3) + r8;
                int ch = 2 * ks + (g & 1);
                ldsm_x4(bfr[nf2][0], bfr[nf2][1], bfr[nf2][2], bfr[nf2][3],
                        Bbase + SWK128(rr, ch));
            }
            #pragma unroll
            for (int mf = 0; mf < 4; mf++)
                #pragma unroll
                for (int nf = 0; nf < 4; nf++)
                    mma_bf16(acc[mf][nf], afr[mf],
                             bfr[nf >> 1][(nf & 1) * 2], bfr[nf >> 1][(nf & 1) * 2 + 1]);
        }

        if (kit == 3) {   // tile done: store f16 scores + fold min (branchless)
            #pragma unroll
            for (int nf = 0; nf < 4; nf++) {
                const int code0 = code_base + nt * 128 + warp_n * 32 + nf * 8 + (lane & 3) * 2;
                const float c2a = __ldg(&g_c2[code0]);
                const float c2b = __ldg(&g_c2[code0 + 1]);
                #pragma unroll
                for (int mf = 0; mf < 4; mf++)
                    #pragma unroll
                    for (int h = 0; h < 2; h++) {
                        const int ridx = mf * 2 + h;
                        const int row = row0 + warp_m * 64 + mf * 16 + h * 8 + (lane >> 2);
                        float v0 = c2a - 2.0f * acc[mf][nf][h * 2 + 0];
                        float v1 = c2b - 2.0f * acc[mf][nf][h * 2 + 1];
                        rmin[ridx] = fminf(rmin[ridx], fminf(v0, v1));
                        *reinterpret_cast<__half2*>(g_dh + (size_t)row * K_ + code0) =
                            __floats2half2_rn(v0, v1);
                    }
            }
        }
    }
    #undef P1_ISSUE

    // block reduce per-row mins (16 owners per row) -> g_pmin[bx][row]
    __syncthreads();
    float* rv = reinterpret_cast<float*>(sm + P1_SM_B);   // [128][16] = 8KB
    const int slot = warp_n * 4 + (lane & 3);
    #pragma unroll
    for (int ridx = 0; ridx < 8; ridx++) {
        const int mf = ridx >> 1, h = ridx & 1;
        const int rl = warp_m * 64 + mf * 16 + h * 8 + (lane >> 2);
        rv[rl * 16 + slot] = rmin[ridx];
    }
    __syncthreads();
    if (tid < 128) {
        float m = rv[tid * 16];
        #pragma unroll
        for (int j = 1; j < 16; j++) m = fminf(m, rv[tid * 16 + j]);
        g_pmin[blockIdx.x * B_ + row0 + tid] = m;
    }
}

// ---------------------------------------------------------------------------
// Phase 2: gmin from g_pmin, one sweep of fp16 scores, exact fp64 rescore
// with reference-grid fp32 rounding + index tie-break. 1 warp per row.
// ---------------------------------------------------------------------------
__global__ __launch_bounds__(256) void phase2_kernel(const float* __restrict__ cb) {
    __shared__ int s_cnt[8];
    __shared__ int s_list[8][CAP];
    const int wid  = threadIdx.x >> 5;
    const int lane = threadIdx.x & 31;
    const int row  = blockIdx.x * 8 + wid;

    float gmin = 3.4e38f;
    if (lane < 8) gmin = g_pmin[lane * B_ + row];
    #pragma unroll
    for (int o = 4; o; o >>= 1) gmin = fminf(gmin, __shfl_xor_sync(0xffffffffu, gmin, o));
    gmin = __shfl_sync(0xffffffffu, gmin, 0);
    const float thr = gmin + MARGIN2;

    if (lane == 0) s_cnt[wid] = 0;
    __syncwarp();

    const uint4* dp = reinterpret_cast<const uint4*>(g_dh + (size_t)row * K_);
    #pragma unroll 4
    for (int i = 0; i < 32; i++) {
        uint4 v = dp[lane + i * 32];
        const int k0 = (lane + i * 32) * 8;
        const uint32_t w[4] = { v.x, v.y, v.z, v.w };
        #pragma unroll
        for (int q = 0; q < 4; q++) {
            __half2 h = *reinterpret_cast<const __half2*>(&w[q]);
            float2 f = __half22float2(h);
            if (f.x < thr) { int p = atomicAdd(&s_cnt[wid], 1); if (p < CAP) s_list[wid][p] = k0 + q * 2; }
            if (f.y < thr) { int p = atomicAdd(&s_cnt[wid], 1); if (p < CAP) s_list[wid][p] = k0 + q * 2 + 1; }
        }
    }
    __syncwarp();
    const int ncand = s_cnt[wid];

    const float* ze = g_ze + (size_t)row * D_;
    const float  zz = g_zz[row];
    float bv = 3.4e38f;
    int   bi = 0x7fffffff;

    if (ncand <= CAP) {
        for (int c = 0; c < ncand; c++) {
            const int k = s_list[wid][c];
            const float* cr = cb + (size_t)k * D_;
            double d = 0.0;
            #pragma unroll
            for (int j = 0; j < 16; j++) {
                int dd = lane + j * 32;
                d = fma((double)ze[dd], (double)cr[dd], d);
            }
            #pragma unroll
            for (int o = 16; o; o >>= 1) d += __shfl_xor_sync(0xffffffffu, d, o);
            float t = __fadd_rn(zz, -2.0f * (float)d);
            float v = __fadd_rn(t, g_c2[k]);
            if (v < bv || (v == bv && k < bi)) { bv = v; bi = k; }
        }
    } else {
        for (int k = 0; k < K_; k++) {
            const float* cr = cb + (size_t)k * D_;
            double d = 0.0;
            #pragma unroll
            for (int j = 0; j < 16; j++) {
                int dd = lane + j * 32;
                d = fma((double)ze[dd], (double)cr[dd], d);
            }
            #pragma unroll
            for (int o = 16; o; o >>= 1) d += __shfl_xor_sync(0xffffffffu, d, o);
            float t = __fadd_rn(zz, -2.0f * (float)d);
            float v = __fadd_rn(t, g_c2[k]);
            if (v < bv || (v == bv && k < bi)) { bv = v; bi = k; }
        }
    }
    if (lane == 0) g_idx[row] = bi;
}

// ---------------------------------------------------------------------------
// Output assembly
// ---------------------------------------------------------------------------
__global__ void output_kernel(const float* __restrict__ cb, float* __restrict__ out) {
    const int b   = blockIdx.x;
    const int tid = threadIdx.x;
    const int idx = g_idx[b];

    const float* ze = g_ze + (size_t)b * D_;
    const float* zq = cb   + (size_t)idx * D_;
    float*       o  = out  + (size_t)b * D_;

    float s = 0.f;
    #pragma unroll
    for (int d = tid; d < D_; d += 128) {
        float e    = ze[d];
        float q    = zq[d];
        float diff = q - e;
        o[d] = e + diff;
        s += diff * diff;
    }
    __shared__ float red[128];
    red[tid] = s;
    __syncthreads();
    #pragma unroll
    for (int o2 = 64; o2; o2 >>= 1) {
        if (tid < o2) red[tid] += red[tid + o2];
        __syncthreads();
    }
    if (tid == 0) {
        out[(size_t)B_ * D_ + b]      = (float)idx;
        out[(size_t)B_ * D_ + B_ + b] = red[0] / (float)D_;
    }
}

// ---------------------------------------------------------------------------
extern "C" void kernel_launch(void* const* d_in, const int* in_sizes, int n_in,
                              void* d_out, int out_size) {
    const float* x  = (const float*)d_in[0];
    const float* W  = (const float*)d_in[1];
    const float* cb = (const float*)d_in[2];
    float* out = (float*)d_out;
    (void)in_sizes; (void)n_in; (void)out_size;

    cudaFuncSetAttribute(gemm1_mma_kernel, cudaFuncAttributeMaxDynamicSharedMemorySize, SM1TOT);
    cudaFuncSetAttribute(phase1_kernel,    cudaFuncAttributeMaxDynamicSharedMemorySize, P1_SMTOT);

    pack_x_kernel<<<B_, 256>>>(x);
    pack_w_kernel<<<D_, 256>>>(W);
    cbprep_kernel<<<K_ / 8, 256>>>(cb);
    gemm1_mma_kernel<<<dim3(4, 128), 256, SM1TOT>>>();
    zz_kernel<<<B_ / 8, 256>>>();
    phase1_kernel<<<dim3(8, 128), 256, P1_SMTOT>>>();
    phase2_kernel<<<B_ / 8, 256>>>(cb);
    output_kernel<<<B_, 128>>>(cb, out);
}

// round 10
// speedup vs baseline: 1.1579x; 1.0067x over previous
#include <cuda_runtime.h>
#include <cuda_bf16.h>
#include <cuda_fp16.h>
#include <cstdint>

// Problem constants
#define B_   16384
#define DIN  1024
#define D_   512
#define K_   8192
#define KP2  3072          // gemm1 packed K: [a0|a0|a1] . [b0|b1|b0]

#define MARGIN2 0.08f      // collect margin incl. f16 quantization slack
#define CAP     32

// ---------------------------------------------------------------------------
// Scratch (device globals; allocations forbidden)
// ---------------------------------------------------------------------------
__device__ float  g_ze[(size_t)B_ * D_];     // z_e fp32
__device__ float  g_c2[K_];
__device__ float  g_zz[B_];
__device__ int    g_idx[B_];
__device__ float  g_pmin[8 * B_];            // per-(code-slice, row) partial min
__device__ __half g_dh[(size_t)B_ * K_];     // approx scores fp16, 256MB
__device__ __nv_bfloat16 g_xs[(size_t)B_ * KP2];   // packed x splits
__device__ __nv_bfloat16 g_ws[(size_t)D_ * KP2];   // packed W splits
__device__ __nv_bfloat16 g_zb[(size_t)B_ * D_];    // bf16(z_e)
__device__ __nv_bfloat16 g_cbb[(size_t)K_ * D_];   // bf16(cb)

// ---------------------------------------------------------------------------
// PTX helpers (baseline PTX only: works at .target sm_100)
// ---------------------------------------------------------------------------
__device__ __forceinline__ uint32_t smem_u32(const void* p) {
    uint32_t a;
    asm("{ .reg .u64 t; cvta.to.shared.u64 t, %1; cvt.u32.u64 %0, t; }" : "=r"(a) : "l"(p));
    return a;
}
__device__ __forceinline__ void cp_async16(uint32_t saddr, const void* gaddr) {
    asm volatile("cp.async.cg.shared.global [%0], [%1], 16;" :: "r"(saddr), "l"(gaddr));
}
__device__ __forceinline__ void cp_commit() { asm volatile("cp.async.commit_group;"); }
__device__ __forceinline__ void cp_wait1()  { asm volatile("cp.async.wait_group 1;" ::: "memory"); }

__device__ __forceinline__ void ldsm_x4(uint32_t& r0, uint32_t& r1, uint32_t& r2, uint32_t& r3,
                                        uint32_t addr) {
    asm volatile("ldmatrix.sync.aligned.m8n8.x4.shared.b16 {%0,%1,%2,%3}, [%4];"
                 : "=r"(r0), "=r"(r1), "=r"(r2), "=r"(r3) : "r"(addr));
}
__device__ __forceinline__ void mma_bf16(float* c, const uint32_t* a, uint32_t b0, uint32_t b1) {
    asm volatile("mma.sync.aligned.m16n8k16.row.col.f32.bf16.bf16.f32 "
                 "{%0,%1,%2,%3}, {%4,%5,%6,%7}, {%8,%9}, {%0,%1,%2,%3};"
                 : "+f"(c[0]), "+f"(c[1]), "+f"(c[2]), "+f"(c[3])
                 : "r"(a[0]), "r"(a[1]), "r"(a[2]), "r"(a[3]), "r"(b0), "r"(b1));
}

// Swizzles:
// A-resident (phase1): 1024B rows, 64 x 16B chunks, XOR within 8-chunk groups
#define SWA(r, c) ((r) * 1024 + ((((c) & 0x38) | (((c) & 7) ^ ((r) & 7))) << 4))
// 128B-row stage tiles (BLK_K=64 bf16): 8 x 16B chunks, XOR by row
#define SWB(r, c) ((r) * 128 + ((((c) ^ ((r) & 7)) & 7) << 4))

// ---------------------------------------------------------------------------
// zz (fp64 accumulation)
// ---------------------------------------------------------------------------
__global__ void zz_kernel() {
    int row  = blockIdx.x * 8 + (threadIdx.x >> 5);
    int lane = threadIdx.x & 31;
    const float* p = g_ze + (size_t)row * D_;
    double s = 0.0;
    #pragma unroll 4
    for (int i = lane; i < D_; i += 32) { double v = (double)p[i]; s += v * v; }
    #pragma unroll
    for (int o = 16; o; o >>= 1) s += __shfl_xor_sync(0xffffffffu, s, o);
    if (lane == 0) g_zz[row] = (float)s;
}

// ---------------------------------------------------------------------------
// Codebook prep: c2 + bf16 pack, single 16MB read. 1 warp per code row.
// ---------------------------------------------------------------------------
__global__ void cbprep_kernel(const float* __restrict__ cb) {
    const int row  = blockIdx.x * 8 + (threadIdx.x >> 5);
    const int lane = threadIdx.x & 31;
    const float4* src = reinterpret_cast<const float4*>(cb + (size_t)row * D_);
    __nv_bfloat162* dst = reinterpret_cast<__nv_bfloat162*>(g_cbb + (size_t)row * D_);
    float s = 0.f;
    #pragma unroll
    for (int j = 0; j < 4; j++) {
        const int i = lane + j * 32;
        float4 v = src[i];
        s += v.x * v.x + v.y * v.y + v.z * v.z + v.w * v.w;
        __nv_bfloat162 h0, h1;
        h0.x = __float2bfloat16_rn(v.x); h0.y = __float2bfloat16_rn(v.y);
        h1.x = __float2bfloat16_rn(v.z); h1.y = __float2bfloat16_rn(v.w);
        dst[i * 2]     = h0;
        dst[i * 2 + 1] = h1;
    }
    #pragma unroll
    for (int o = 16; o; o >>= 1) s += __shfl_xor_sync(0xffffffffu, s, o);
    if (lane == 0) g_c2[row] = s;
}

// ---------------------------------------------------------------------------
// Pack kernels for gemm1 operands (bf16 3-split)
// ---------------------------------------------------------------------------
__global__ void pack_x_kernel(const float* __restrict__ x) {
    const int row = blockIdx.x, t = threadIdx.x;
    float4 v = *reinterpret_cast<const float4*>(x + (size_t)row * DIN + t * 4);
    __nv_bfloat162 h01, h23, l01, l23;
    h01.x = __float2bfloat16_rn(v.x); h01.y = __float2bfloat16_rn(v.y);
    h23.x = __float2bfloat16_rn(v.z); h23.y = __float2bfloat16_rn(v.w);
    l01.x = __float2bfloat16_rn(v.x - __bfloat162float(h01.x));
    l01.y = __float2bfloat16_rn(v.y - __bfloat162float(h01.y));
    l23.x = __float2bfloat16_rn(v.z - __bfloat162float(h23.x));
    l23.y = __float2bfloat16_rn(v.w - __bfloat162float(h23.y));
    __nv_bfloat162* d = reinterpret_cast<__nv_bfloat162*>(g_xs + (size_t)row * KP2 + t * 4);
    d[0] = h01; d[1] = h23;
    d += 512;  d[0] = h01; d[1] = h23;
    d += 512;  d[0] = l01; d[1] = l23;
}

__global__ void pack_w_kernel(const float* __restrict__ w) {
    const int row = blockIdx.x, t = threadIdx.x;
    float4 v = *reinterpret_cast<const float4*>(w + (size_t)row * DIN + t * 4);
    __nv_bfloat162 h01, h23, l01, l23;
    h01.x = __float2bfloat16_rn(v.x); h01.y = __float2bfloat16_rn(v.y);
    h23.x = __float2bfloat16_rn(v.z); h23.y = __float2bfloat16_rn(v.w);
    l01.x = __float2bfloat16_rn(v.x - __bfloat162float(h01.x));
    l01.y = __float2bfloat16_rn(v.y - __bfloat162float(h01.y));
    l23.x = __float2bfloat16_rn(v.z - __bfloat162float(h23.x));
    l23.y = __float2bfloat16_rn(v.w - __bfloat162float(h23.y));
    __nv_bfloat162* d = reinterpret_cast<__nv_bfloat162*>(g_ws + (size_t)row * KP2 + t * 4);
    d[0] = h01; d[1] = h23;
    d += 512;  d[0] = l01; d[1] = l23;
    d += 512;  d[0] = h01; d[1] = h23;
}

// ---------------------------------------------------------------------------
// GEMM1 via mma.sync: z_e = x @ W^T with packed 3-split (K''=3072).
// 128-thread CTAs, M-tile 64, 2 CTAs/SM. BLK_K=64, 3-stage cp.async.
// grid (4, 256). Epilogue also emits bf16(z_e).
// ---------------------------------------------------------------------------
#define G1_SA   8192                 // A stage bytes (64 x 128B)
#define G1_SB   16384                // B stage bytes (128 x 128B)
#define G1_BOFF (3 * G1_SA)          // 24576
#define SM1TOT  (3 * G1_SA + 3 * G1_SB)   // 73728 per CTA

__global__ __launch_bounds__(128, 2) void gemm1_mma_kernel() {
    extern __shared__ char sm[];
    const uint32_t sbase = smem_u32(sm);
    const int tid  = threadIdx.x;
    const int lane = tid & 31;
    const int warp_n = tid >> 5;       // 0..3
    const int row0 = blockIdx.y * 64;
    const int col0 = blockIdx.x * 128;
    const int NKIT = KP2 / 64;         // 48

    const __nv_bfloat16* gA = g_xs + (size_t)row0 * KP2;
    const __nv_bfloat16* gB = g_ws + (size_t)col0 * KP2;

    float acc[4][4][4];
    #pragma unroll
    for (int mf = 0; mf < 4; mf++)
        #pragma unroll
        for (int nf = 0; nf < 4; nf++)
            #pragma unroll
            for (int q = 0; q < 4; q++) acc[mf][nf][q] = 0.f;

    #define G1_ISSUE(stg, kit) do {                                               \
        const uint32_t As_ = sbase + (stg) * G1_SA;                               \
        const uint32_t Bs_ = sbase + G1_BOFF + (stg) * G1_SB;                     \
        const int koff_ = (kit) * 64;                                             \
        _Pragma("unroll")                                                          \
        for (int i_ = 0; i_ < 4; i_++) {                                           \
            int id_ = tid + i_ * 128;                                              \
            int r_  = id_ >> 3;                                                    \
            int c_  = id_ & 7;                                                     \
            cp_async16(As_ + SWB(r_, c_), gA + (size_t)r_ * KP2 + koff_ + c_ * 8); \
        }                                                                          \
        _Pragma("unroll")                                                          \
        for (int i_ = 0; i_ < 8; i_++) {                                           \
            int id_ = tid + i_ * 128;                                              \
            int r_  = id_ >> 3;                                                    \
            int c_  = id_ & 7;                                                     \
            cp_async16(Bs_ + SWB(r_, c_), gB + (size_t)r_ * KP2 + koff_ + c_ * 8); \
        }                                                                          \
    } while (0)

    G1_ISSUE(0, 0); cp_commit();
    G1_ISSUE(1, 1); cp_commit();

    const int g = lane >> 3;
    const int r8 = lane & 7;

    for (int kit = 0; kit < NKIT; kit++) {
        cp_wait1();
        __syncthreads();
        if (kit + 2 < NKIT) G1_ISSUE((kit + 2) % 3, kit + 2);
        cp_commit();

        const int stg = kit % 3;
        const uint32_t Abase = sbase + stg * G1_SA;
        const uint32_t Bbase = sbase + G1_BOFF + stg * G1_SB;

        #pragma unroll
        for (int ks = 0; ks < 4; ks++) {
            uint32_t afr[4][4];
            #pragma unroll
            for (int mf = 0; mf < 4; mf++) {
                int rr = mf * 16 + ((g & 1) << 3) + r8;
                int ch = 2 * ks + (g >> 1);
                ldsm_x4(afr[mf][0], afr[mf][1], afr[mf][2], afr[mf][3],
                        Abase + SWB(rr, ch));
            }
            uint32_t bfr[2][4];
            #pragma unroll
            for (int nf2 = 0; nf2 < 2; nf2++) {
                int rr = warp_n * 32 + nf2 * 16 + ((g >> 1) << 3) + r8;
                int ch = 2 * ks + (g & 1);
                ldsm_x4(bfr[nf2][0], bfr[nf2][1], bfr[nf2][2], bfr[nf2][3],
                        Bbase + SWB(rr, ch));
            }
            #pragma unroll
            for (int mf = 0; mf < 4; mf++)
                #pragma unroll
                for (int nf = 0; nf < 4; nf++)
                    mma_bf16(acc[mf][nf], afr[mf],
                             bfr[nf >> 1][(nf & 1) * 2], bfr[nf >> 1][(nf & 1) * 2 + 1]);
        }
    }
    #undef G1_ISSUE

    #pragma unroll
    for (int mf = 0; mf < 4; mf++)
        #pragma unroll
        for (int h = 0; h < 2; h++) {
            const int row = row0 + mf * 16 + h * 8 + (lane >> 2);
            #pragma unroll
            for (int nf = 0; nf < 4; nf++) {
                const int col = col0 + warp_n * 32 + nf * 8 + (lane & 3) * 2;
                float2 o; o.x = acc[mf][nf][h * 2]; o.y = acc[mf][nf][h * 2 + 1];
                *reinterpret_cast<float2*>(g_ze + (size_t)row * D_ + col) = o;
                __nv_bfloat162 hb;
                hb.x = __float2bfloat16_rn(o.x); hb.y = __float2bfloat16_rn(o.y);
                *reinterpret_cast<__nv_bfloat162*>(g_zb + (size_t)row * D_ + col) = hb;
            }
        }
}

// ---------------------------------------------------------------------------
// Phase 1: single-pass bf16 approx GEMM. 128-thread CTAs, M-tile 64,
// 2 CTAs/SM. A resident (64KB swizzled), B streamed 16KB x 3 stages.
// Stores fp16 scores s = c2 - 2*dot + branchless running min -> g_pmin.
// grid (8, 256).
// ---------------------------------------------------------------------------
#define P1_SM_A  0
#define P1_SM_B  65536
#define P1_SB    16384
#define P1_SMTOT (65536 + 3 * P1_SB)   // 114688 per CTA -> 2/SM

__global__ __launch_bounds__(128, 2) void phase1_kernel() {
    extern __shared__ char sm[];
    const uint32_t sbase = smem_u32(sm);
    const int tid  = threadIdx.x;
    const int lane = tid & 31;
    const int warp_n = tid >> 5;       // 0..3
    const int row0 = blockIdx.y * 64;
    const int code_base = blockIdx.x * 1024;

    // resident A: 64 rows x 64 chunks(16B)
    {
        const __nv_bfloat16* gA = g_zb + (size_t)row0 * D_;
        #pragma unroll
        for (int i = 0; i < 32; i++) {
            int idx = tid + i * 128;
            int r   = idx >> 6;
            int c16 = idx & 63;
            cp_async16(sbase + P1_SM_A + SWA(r, c16), gA + (size_t)r * D_ + c16 * 8);
        }
    }
    cp_commit();

    #define P1_ISSUE(stg, u) do {                                                  \
        const uint32_t Bs_ = sbase + P1_SM_B + (stg) * P1_SB;                      \
        const int nt_ = (u) >> 3, kit_ = (u) & 7;                                  \
        const __nv_bfloat16* gB_ = g_cbb + (size_t)(code_base + nt_ * 128) * D_;   \
        _Pragma("unroll")                                                          \
        for (int i_ = 0; i_ < 8; i_++) {                                           \
            int id_ = tid + i_ * 128;                                              \
            int r_  = id_ >> 3;                                                    \
            int c_  = id_ & 7;                                                     \
            cp_async16(Bs_ + SWB(r_, c_),                                          \
                       gB_ + (size_t)r_ * D_ + kit_ * 64 + c_ * 8);                \
        }                                                                          \
    } while (0)

    P1_ISSUE(0, 0); cp_commit();
    P1_ISSUE(1, 1); cp_commit();

    const int g = lane >> 3;
    const int r8 = lane & 7;
    float acc[4][4][4];
    float rmin[8];
    #pragma unroll
    for (int i = 0; i < 8; i++) rmin[i] = 3.4e38f;

    for (int u = 0; u < 64; u++) {
        const int nt = u >> 3, kit = u & 7;
        cp_wait1();
        __syncthreads();
        if (u + 2 < 64) P1_ISSUE((u + 2) % 3, u + 2);
        cp_commit();

        if (kit == 0) {
            #pragma unroll
            for (int mf = 0; mf < 4; mf++)
                #pragma unroll
                for (int nf = 0; nf < 4; nf++)
                    #pragma unroll
                    for (int q = 0; q < 4; q++) acc[mf][nf][q] = 0.f;
        }

        const uint32_t Bbase = sbase + P1_SM_B + (u % 3) * P1_SB;
        #pragma unroll
        for (int ks = 0; ks < 4; ks++) {
            uint32_t afr[4][4];
            #pragma unroll
            for (int mf = 0; mf < 4; mf++) {
                int rr  = mf * 16 + ((g & 1) << 3) + r8;
                int c16 = kit * 8 + 2 * ks + (g >> 1);
                ldsm_x4(afr[mf][0], afr[mf][1], afr[mf][2], afr[mf][3],
                        sbase + P1_SM_A + SWA(rr, c16));
            }
            uint32_t bfr[2][4];
            #pragma unroll
            for (int nf2 = 0; nf2 < 2; nf2++) {
                int rr = warp_n * 32 + nf2 * 16 + ((g >> 1) << 3) + r8;
                int ch = 2 * ks + (g & 1);
                ldsm_x4(bfr[nf2][0], bfr[nf2][1], bfr[nf2][2], bfr[nf2][3],
                        Bbase + SWB(rr, ch));
            }
            #pragma unroll
            for (int mf = 0; mf < 4; mf++)
                #pragma unroll
                for (int nf = 0; nf < 4; nf++)
                    mma_bf16(acc[mf][nf], afr[mf],
                             bfr[nf >> 1][(nf & 1) * 2], bfr[nf >> 1][(nf & 1) * 2 + 1]);
        }

        if (kit == 7) {   // tile done: store f16 scores + fold min (branchless)
            #pragma unroll
            for (int nf = 0; nf < 4; nf++) {
                const int code0 = code_base + nt * 128 + warp_n * 32 + nf * 8 + (lane & 3) * 2;
                const float c2a = __ldg(&g_c2[code0]);
                const float c2b = __ldg(&g_c2[code0 + 1]);
                #pragma unroll
                for (int mf = 0; mf < 4; mf++)
                    #pragma unroll
                    for (int h = 0; h < 2; h++) {
                        const int ridx = mf * 2 + h;
                        const int row = row0 + mf * 16 + h * 8 + (lane >> 2);
                        float v0 = c2a - 2.0f * acc[mf][nf][h * 2 + 0];
                        float v1 = c2b - 2.0f * acc[mf][nf][h * 2 + 1];
                        rmin[ridx] = fminf(rmin[ridx], fminf(v0, v1));
                        *reinterpret_cast<__half2*>(g_dh + (size_t)row * K_ + code0) =
                            __floats2half2_rn(v0, v1);
                    }
            }
        }
    }
    #undef P1_ISSUE

    // block reduce per-row mins (16 owners per row) -> g_pmin[bx][row]
    __syncthreads();
    float* rv = reinterpret_cast<float*>(sm + P1_SM_B);   // [64][16] = 4KB
    const int slot = warp_n * 4 + (lane & 3);
    #pragma unroll
    for (int ridx = 0; ridx < 8; ridx++) {
        const int mf = ridx >> 1, h = ridx & 1;
        const int rl = mf * 16 + h * 8 + (lane >> 2);
        rv[rl * 16 + slot] = rmin[ridx];
    }
    __syncthreads();
    if (tid < 64) {
        float m = rv[tid * 16];
        #pragma unroll
        for (int j = 1; j < 16; j++) m = fminf(m, rv[tid * 16 + j]);
        g_pmin[blockIdx.x * B_ + row0 + tid] = m;
    }
}

// ---------------------------------------------------------------------------
// Phase 2 (fused with output): gmin from g_pmin, one sweep of fp16 scores,
// exact fp64 rescore (reference-grid fp32 rounding + index tie-break),
// then the owning warp writes z_q_st row, index, and vq_loss. 1 warp/row.
// ---------------------------------------------------------------------------
__global__ __launch_bounds__(256) void phase2_kernel(const float* __restrict__ cb,
                                                     float* __restrict__ out) {
    __shared__ int s_cnt[8];
    __shared__ int s_list[8][CAP];
    const int wid  = threadIdx.x >> 5;
    const int lane = threadIdx.x & 31;
    const int row  = blockIdx.x * 8 + wid;

    float gmin = 3.4e38f;
    if (lane < 8) gmin = g_pmin[lane * B_ + row];
    #pragma unroll
    for (int o = 4; o; o >>= 1) gmin = fminf(gmin, __shfl_xor_sync(0xffffffffu, gmin, o));
    gmin = __shfl_sync(0xffffffffu, gmin, 0);
    const float thr = gmin + MARGIN2;

    if (lane == 0) s_cnt[wid] = 0;
    __syncwarp();

    const uint4* dp = reinterpret_cast<const uint4*>(g_dh + (size_t)row * K_);
    #pragma unroll 4
    for (int i = 0; i < 32; i++) {
        uint4 v = dp[lane + i * 32];
        const int k0 = (lane + i * 32) * 8;
        const uint32_t w[4] = { v.x, v.y, v.z, v.w };
        #pragma unroll
        for (int q = 0; q < 4; q++) {
            __half2 h = *reinterpret_cast<const __half2*>(&w[q]);
            float2 f = __half22float2(h);
            if (f.x < thr) { int p = atomicAdd(&s_cnt[wid], 1); if (p < CAP) s_list[wid][p] = k0 + q * 2; }
            if (f.y < thr) { int p = atomicAdd(&s_cnt[wid], 1); if (p < CAP) s_list[wid][p] = k0 + q * 2 + 1; }
        }
    }
    __syncwarp();
    const int ncand = s_cnt[wid];

    const float* ze = g_ze + (size_t)row * D_;
    const float  zz = g_zz[row];
    float bv = 3.4e38f;
    int   bi = 0x7fffffff;

    if (ncand <= CAP) {
        for (int c = 0; c < ncand; c++) {
            const int k = s_list[wid][c];
            const float* cr = cb + (size_t)k * D_;
            double d = 0.0;
            #pragma unroll
            for (int j = 0; j < 16; j++) {
                int dd = lane + j * 32;
                d = fma((double)ze[dd], (double)cr[dd], d);
            }
            #pragma unroll
            for (int o = 16; o; o >>= 1) d += __shfl_xor_sync(0xffffffffu, d, o);
            float t = __fadd_rn(zz, -2.0f * (float)d);
            float v = __fadd_rn(t, g_c2[k]);
            if (v < bv || (v == bv && k < bi)) { bv = v; bi = k; }
        }
    } else {
        for (int k = 0; k < K_; k++) {
            const float* cr = cb + (size_t)k * D_;
            double d = 0.0;
            #pragma unroll
            for (int j = 0; j < 16; j++) {
                int dd = lane + j * 32;
                d = fma((double)ze[dd], (double)cr[dd], d);
            }
            #pragma unroll
            for (int o = 16; o; o >>= 1) d += __shfl_xor_sync(0xffffffffu, d, o);
            float t = __fadd_rn(zz, -2.0f * (float)d);
            float v = __fadd_rn(t, g_c2[k]);
            if (v < bv || (v == bv && k < bi)) { bv = v; bi = k; }
        }
    }
    bi = __shfl_sync(0xffffffffu, bi, 0);

    // fused output: z_q_st row + loss + index
    const float* zq = cb + (size_t)bi * D_;
    float* o = out + (size_t)row * D_;
    float s = 0.f;
    #pragma unroll
    for (int j = 0; j < 16; j++) {
        const int d = lane + j * 32;
        float e    = ze[d];
        float q    = zq[d];
        float diff = q - e;
        o[d] = e + diff;
        s += diff * diff;
    }
    #pragma unroll
    for (int off = 16; off; off >>= 1) s += __shfl_xor_sync(0xffffffffu, s, off);
    if (lane == 0) {
        g_idx[row] = bi;
        out[(size_t)B_ * D_ + row]      = (float)bi;
        out[(size_t)B_ * D_ + B_ + row] = s / (float)D_;
    }
}

// ---------------------------------------------------------------------------
extern "C" void kernel_launch(void* const* d_in, const int* in_sizes, int n_in,
                              void* d_out, int out_size) {
    const float* x  = (const float*)d_in[0];
    const float* W  = (const float*)d_in[1];
    const float* cb = (const float*)d_in[2];
    float* out = (float*)d_out;
    (void)in_sizes; (void)n_in; (void)out_size;

    cudaFuncSetAttribute(gemm1_mma_kernel, cudaFuncAttributeMaxDynamicSharedMemorySize, SM1TOT);
    cudaFuncSetAttribute(phase1_kernel,    cudaFuncAttributeMaxDynamicSharedMemorySize, P1_SMTOT);

    pack_x_kernel<<<B_, 256>>>(x);
    pack_w_kernel<<<D_, 256>>>(W);
    cbprep_kernel<<<K_ / 8, 256>>>(cb);
    gemm1_mma_kernel<<<dim3(4, 256), 128, SM1TOT>>>();
    zz_kernel<<<B_ / 8, 256>>>();
    phase1_kernel<<<dim3(8, 256), 128, P1_SMTOT>>>();
    phase2_kernel<<<B_ / 8, 256>>>(cb, out);
}

// round 11
// speedup vs baseline: 1.2720x; 1.0985x over previous
#include <cuda_runtime.h>
#include <cuda_bf16.h>
#include <cuda_fp16.h>
#include <cstdint>

// Problem constants
#define B_   16384
#define DIN  1024
#define D_   512
#define K_   8192
#define KP2  3072          // gemm1 packed K: [a0|a0|a1] . [b0|b1|b0]

#define MARGIN2 0.08f      // bf16 approx-score collect margin (2-sided 7sigma)
#define CAP     32

// ---------------------------------------------------------------------------
// Scratch (device globals; allocations forbidden)
// ---------------------------------------------------------------------------
__device__ float  g_ze[(size_t)B_ * D_];     // z_e fp32
__device__ float  g_c2[K_];
__device__ float  g_zz[B_];
__device__ int    g_idx[B_];
__device__ uint4  g_top[(size_t)8 * B_ * 16];      // per-(xblk,row,slot) top-2, 32MB
__device__ __nv_bfloat16 g_xs[(size_t)B_ * KP2];   // packed x splits
__device__ __nv_bfloat16 g_ws[(size_t)D_ * KP2];   // packed W splits
__device__ __nv_bfloat16 g_zb[(size_t)B_ * D_];    // bf16(z_e)
__device__ __nv_bfloat16 g_cbb[(size_t)K_ * D_];   // bf16(cb)

// ---------------------------------------------------------------------------
// PTX helpers (baseline PTX only: works at .target sm_100)
// ---------------------------------------------------------------------------
__device__ __forceinline__ uint32_t smem_u32(const void* p) {
    uint32_t a;
    asm("{ .reg .u64 t; cvta.to.shared.u64 t, %1; cvt.u32.u64 %0, t; }" : "=r"(a) : "l"(p));
    return a;
}
__device__ __forceinline__ void cp_async16(uint32_t saddr, const void* gaddr) {
    asm volatile("cp.async.cg.shared.global [%0], [%1], 16;" :: "r"(saddr), "l"(gaddr));
}
__device__ __forceinline__ void cp_commit() { asm volatile("cp.async.commit_group;"); }
__device__ __forceinline__ void cp_wait1()  { asm volatile("cp.async.wait_group 1;" ::: "memory"); }

__device__ __forceinline__ void ldsm_x4(uint32_t& r0, uint32_t& r1, uint32_t& r2, uint32_t& r3,
                                        uint32_t addr) {
    asm volatile("ldmatrix.sync.aligned.m8n8.x4.shared.b16 {%0,%1,%2,%3}, [%4];"
                 : "=r"(r0), "=r"(r1), "=r"(r2), "=r"(r3) : "r"(addr));
}
__device__ __forceinline__ void mma_bf16(float* c, const uint32_t* a, uint32_t b0, uint32_t b1) {
    asm volatile("mma.sync.aligned.m16n8k16.row.col.f32.bf16.bf16.f32 "
                 "{%0,%1,%2,%3}, {%4,%5,%6,%7}, {%8,%9}, {%0,%1,%2,%3};"
                 : "+f"(c[0]), "+f"(c[1]), "+f"(c[2]), "+f"(c[3])
                 : "r"(a[0]), "r"(a[1]), "r"(a[2]), "r"(a[3]), "r"(b0), "r"(b1));
}

// Swizzles:
// A-resident (phase1): 1024B rows, 64 x 16B chunks, XOR within 8-chunk groups
#define SWA(r, c) ((r) * 1024 + ((((c) & 0x38) | (((c) & 7) ^ ((r) & 7))) << 4))
// 128B-row stage tiles (BLK_K=64 bf16): 8 x 16B chunks, XOR by row
#define SWB(r, c) ((r) * 128 + ((((c) ^ ((r) & 7)) & 7) << 4))

// ---------------------------------------------------------------------------
// zz (fp64 accumulation)
// ---------------------------------------------------------------------------
__global__ void zz_kernel() {
    int row  = blockIdx.x * 8 + (threadIdx.x >> 5);
    int lane = threadIdx.x & 31;
    const float* p = g_ze + (size_t)row * D_;
    double s = 0.0;
    #pragma unroll 4
    for (int i = lane; i < D_; i += 32) { double v = (double)p[i]; s += v * v; }
    #pragma unroll
    for (int o = 16; o; o >>= 1) s += __shfl_xor_sync(0xffffffffu, s, o);
    if (lane == 0) g_zz[row] = (float)s;
}

// ---------------------------------------------------------------------------
// Codebook prep: c2 + bf16 pack, single 16MB read. 1 warp per code row.
// ---------------------------------------------------------------------------
__global__ void cbprep_kernel(const float* __restrict__ cb) {
    const int row  = blockIdx.x * 8 + (threadIdx.x >> 5);
    const int lane = threadIdx.x & 31;
    const float4* src = reinterpret_cast<const float4*>(cb + (size_t)row * D_);
    __nv_bfloat162* dst = reinterpret_cast<__nv_bfloat162*>(g_cbb + (size_t)row * D_);
    float s = 0.f;
    #pragma unroll
    for (int j = 0; j < 4; j++) {
        const int i = lane + j * 32;
        float4 v = src[i];
        s += v.x * v.x + v.y * v.y + v.z * v.z + v.w * v.w;
        __nv_bfloat162 h0, h1;
        h0.x = __float2bfloat16_rn(v.x); h0.y = __float2bfloat16_rn(v.y);
        h1.x = __float2bfloat16_rn(v.z); h1.y = __float2bfloat16_rn(v.w);
        dst[i * 2]     = h0;
        dst[i * 2 + 1] = h1;
    }
    #pragma unroll
    for (int o = 16; o; o >>= 1) s += __shfl_xor_sync(0xffffffffu, s, o);
    if (lane == 0) g_c2[row] = s;
}

// ---------------------------------------------------------------------------
// Pack kernels for gemm1 operands (bf16 3-split)
// ---------------------------------------------------------------------------
__global__ void pack_x_kernel(const float* __restrict__ x) {
    const int row = blockIdx.x, t = threadIdx.x;
    float4 v = *reinterpret_cast<const float4*>(x + (size_t)row * DIN + t * 4);
    __nv_bfloat162 h01, h23, l01, l23;
    h01.x = __float2bfloat16_rn(v.x); h01.y = __float2bfloat16_rn(v.y);
    h23.x = __float2bfloat16_rn(v.z); h23.y = __float2bfloat16_rn(v.w);
    l01.x = __float2bfloat16_rn(v.x - __bfloat162float(h01.x));
    l01.y = __float2bfloat16_rn(v.y - __bfloat162float(h01.y));
    l23.x = __float2bfloat16_rn(v.z - __bfloat162float(h23.x));
    l23.y = __float2bfloat16_rn(v.w - __bfloat162float(h23.y));
    __nv_bfloat162* d = reinterpret_cast<__nv_bfloat162*>(g_xs + (size_t)row * KP2 + t * 4);
    d[0] = h01; d[1] = h23;
    d += 512;  d[0] = h01; d[1] = h23;
    d += 512;  d[0] = l01; d[1] = l23;
}

__global__ void pack_w_kernel(const float* __restrict__ w) {
    const int row = blockIdx.x, t = threadIdx.x;
    float4 v = *reinterpret_cast<const float4*>(w + (size_t)row * DIN + t * 4);
    __nv_bfloat162 h01, h23, l01, l23;
    h01.x = __float2bfloat16_rn(v.x); h01.y = __float2bfloat16_rn(v.y);
    h23.x = __float2bfloat16_rn(v.z); h23.y = __float2bfloat16_rn(v.w);
    l01.x = __float2bfloat16_rn(v.x - __bfloat162float(h01.x));
    l01.y = __float2bfloat16_rn(v.y - __bfloat162float(h01.y));
    l23.x = __float2bfloat16_rn(v.z - __bfloat162float(h23.x));
    l23.y = __float2bfloat16_rn(v.w - __bfloat162float(h23.y));
    __nv_bfloat162* d = reinterpret_cast<__nv_bfloat162*>(g_ws + (size_t)row * KP2 + t * 4);
    d[0] = h01; d[1] = h23;
    d += 512;  d[0] = l01; d[1] = l23;
    d += 512;  d[0] = h01; d[1] = h23;
}

// ---------------------------------------------------------------------------
// GEMM1 via mma.sync: z_e = x @ W^T with packed 3-split (K''=3072).
// 128-thread CTAs, M-tile 64, 2 CTAs/SM. BLK_K=64, 3-stage cp.async.
// grid (4, 256). Epilogue also emits bf16(z_e).
// ---------------------------------------------------------------------------
#define G1_SA   8192                 // A stage bytes (64 x 128B)
#define G1_SB   16384                // B stage bytes (128 x 128B)
#define G1_BOFF (3 * G1_SA)          // 24576
#define SM1TOT  (3 * G1_SA + 3 * G1_SB)   // 73728 per CTA

__global__ __launch_bounds__(128, 2) void gemm1_mma_kernel() {
    extern __shared__ char sm[];
    const uint32_t sbase = smem_u32(sm);
    const int tid  = threadIdx.x;
    const int lane = tid & 31;
    const int warp_n = tid >> 5;       // 0..3
    const int row0 = blockIdx.y * 64;
    const int col0 = blockIdx.x * 128;
    const int NKIT = KP2 / 64;         // 48

    const __nv_bfloat16* gA = g_xs + (size_t)row0 * KP2;
    const __nv_bfloat16* gB = g_ws + (size_t)col0 * KP2;

    float acc[4][4][4];
    #pragma unroll
    for (int mf = 0; mf < 4; mf++)
        #pragma unroll
        for (int nf = 0; nf < 4; nf++)
            #pragma unroll
            for (int q = 0; q < 4; q++) acc[mf][nf][q] = 0.f;

    #define G1_ISSUE(stg, kit) do {                                               \
        const uint32_t As_ = sbase + (stg) * G1_SA;                               \
        const uint32_t Bs_ = sbase + G1_BOFF + (stg) * G1_SB;                     \
        const int koff_ = (kit) * 64;                                             \
        _Pragma("unroll")                                                          \
        for (int i_ = 0; i_ < 4; i_++) {                                           \
            int id_ = tid + i_ * 128;                                              \
            int r_  = id_ >> 3;                                                    \
            int c_  = id_ & 7;                                                     \
            cp_async16(As_ + SWB(r_, c_), gA + (size_t)r_ * KP2 + koff_ + c_ * 8); \
        }                                                                          \
        _Pragma("unroll")                                                          \
        for (int i_ = 0; i_ < 8; i_++) {                                           \
            int id_ = tid + i_ * 128;                                              \
            int r_  = id_ >> 3;                                                    \
            int c_  = id_ & 7;                                                     \
            cp_async16(Bs_ + SWB(r_, c_), gB + (size_t)r_ * KP2 + koff_ + c_ * 8); \
        }                                                                          \
    } while (0)

    G1_ISSUE(0, 0); cp_commit();
    G1_ISSUE(1, 1); cp_commit();

    const int g = lane >> 3;
    const int r8 = lane & 7;

    for (int kit = 0; kit < NKIT; kit++) {
        cp_wait1();
        __syncthreads();
        if (kit + 2 < NKIT) G1_ISSUE((kit + 2) % 3, kit + 2);
        cp_commit();

        const int stg = kit % 3;
        const uint32_t Abase = sbase + stg * G1_SA;
        const uint32_t Bbase = sbase + G1_BOFF + stg * G1_SB;

        #pragma unroll
        for (int ks = 0; ks < 4; ks++) {
            uint32_t afr[4][4];
            #pragma unroll
            for (int mf = 0; mf < 4; mf++) {
                int rr = mf * 16 + ((g & 1) << 3) + r8;
                int ch = 2 * ks + (g >> 1);
                ldsm_x4(afr[mf][0], afr[mf][1], afr[mf][2], afr[mf][3],
                        Abase + SWB(rr, ch));
            }
            uint32_t bfr[2][4];
            #pragma unroll
            for (int nf2 = 0; nf2 < 2; nf2++) {
                int rr = warp_n * 32 + nf2 * 16 + ((g >> 1) << 3) + r8;
                int ch = 2 * ks + (g & 1);
                ldsm_x4(bfr[nf2][0], bfr[nf2][1], bfr[nf2][2], bfr[nf2][3],
                        Bbase + SWB(rr, ch));
            }
            #pragma unroll
            for (int mf = 0; mf < 4; mf++)
                #pragma unroll
                for (int nf = 0; nf < 4; nf++)
                    mma_bf16(acc[mf][nf], afr[mf],
                             bfr[nf >> 1][(nf & 1) * 2], bfr[nf >> 1][(nf & 1) * 2 + 1]);
        }
    }
    #undef G1_ISSUE

    #pragma unroll
    for (int mf = 0; mf < 4; mf++)
        #pragma unroll
        for (int h = 0; h < 2; h++) {
            const int row = row0 + mf * 16 + h * 8 + (lane >> 2);
            #pragma unroll
            for (int nf = 0; nf < 4; nf++) {
                const int col = col0 + warp_n * 32 + nf * 8 + (lane & 3) * 2;
                float2 o; o.x = acc[mf][nf][h * 2]; o.y = acc[mf][nf][h * 2 + 1];
                *reinterpret_cast<float2*>(g_ze + (size_t)row * D_ + col) = o;
                __nv_bfloat162 hb;
                hb.x = __float2bfloat16_rn(o.x); hb.y = __float2bfloat16_rn(o.y);
                *reinterpret_cast<__nv_bfloat162*>(g_zb + (size_t)row * D_ + col) = hb;
            }
        }
}

// ---------------------------------------------------------------------------
// Phase 1: single-pass bf16 approx GEMM with BRANCHLESS per-owner top-2.
// 128-thread CTAs, M-tile 64, 2 CTAs/SM. A resident (64KB), B streamed
// 16KB x 3. Each (thread,row-slot) owner keeps (v1,i1,v2,i2) over its
// 128 codes; stored as one uint4 per owner -> g_top (32MB total).
// grid (8, 256).
// ---------------------------------------------------------------------------
#define P1_SM_A  0
#define P1_SM_B  65536
#define P1_SB    16384
#define P1_SMTOT (65536 + 3 * P1_SB)   // 114688 per CTA -> 2/SM

__global__ __launch_bounds__(128, 2) void phase1_kernel() {
    extern __shared__ char sm[];
    const uint32_t sbase = smem_u32(sm);
    const int tid  = threadIdx.x;
    const int lane = tid & 31;
    const int warp_n = tid >> 5;       // 0..3
    const int row0 = blockIdx.y * 64;
    const int code_base = blockIdx.x * 1024;

    // resident A: 64 rows x 64 chunks(16B)
    {
        const __nv_bfloat16* gA = g_zb + (size_t)row0 * D_;
        #pragma unroll
        for (int i = 0; i < 32; i++) {
            int idx = tid + i * 128;
            int r   = idx >> 6;
            int c16 = idx & 63;
            cp_async16(sbase + P1_SM_A + SWA(r, c16), gA + (size_t)r * D_ + c16 * 8);
        }
    }
    cp_commit();

    #define P1_ISSUE(stg, u) do {                                                  \
        const uint32_t Bs_ = sbase + P1_SM_B + (stg) * P1_SB;                      \
        const int nt_ = (u) >> 3, kit_ = (u) & 7;                                  \
        const __nv_bfloat16* gB_ = g_cbb + (size_t)(code_base + nt_ * 128) * D_;   \
        _Pragma("unroll")                                                          \
        for (int i_ = 0; i_ < 8; i_++) {                                           \
            int id_ = tid + i_ * 128;                                              \
            int r_  = id_ >> 3;                                                    \
            int c_  = id_ & 7;                                                     \
            cp_async16(Bs_ + SWB(r_, c_),                                          \
                       gB_ + (size_t)r_ * D_ + kit_ * 64 + c_ * 8);                \
        }                                                                          \
    } while (0)

    P1_ISSUE(0, 0); cp_commit();
    P1_ISSUE(1, 1); cp_commit();

    const int g = lane >> 3;
    const int r8 = lane & 7;
    float acc[4][4][4];

    // per-owner top-2 (8 row-slots per thread), branchless updates only
    float tv1[8], tv2[8];
    int   ti1[8], ti2[8];
    #pragma unroll
    for (int i = 0; i < 8; i++) {
        tv1[i] = 3.4e38f; tv2[i] = 3.4e38f;
        ti1[i] = 0x7fffffff; ti2[i] = 0x7fffffff;
    }

    #define TOP2(v, k, r) do {                                                     \
        const bool l1_ = (v) < tv1[r];                                             \
        const bool l2_ = (v) < tv2[r];                                             \
        const float nv2_ = l1_ ? tv1[r] : (l2_ ? (v) : tv2[r]);                    \
        const int   ni2_ = l1_ ? ti1[r] : (l2_ ? (k) : ti2[r]);                    \
        tv1[r] = l1_ ? (v) : tv1[r];                                               \
        ti1[r] = l1_ ? (k) : ti1[r];                                               \
        tv2[r] = nv2_; ti2[r] = ni2_;                                              \
    } while (0)

    for (int u = 0; u < 64; u++) {
        const int nt = u >> 3, kit = u & 7;
        cp_wait1();
        __syncthreads();
        if (u + 2 < 64) P1_ISSUE((u + 2) % 3, u + 2);
        cp_commit();

        if (kit == 0) {
            #pragma unroll
            for (int mf = 0; mf < 4; mf++)
                #pragma unroll
                for (int nf = 0; nf < 4; nf++)
                    #pragma unroll
                    for (int q = 0; q < 4; q++) acc[mf][nf][q] = 0.f;
        }

        const uint32_t Bbase = sbase + P1_SM_B + (u % 3) * P1_SB;
        #pragma unroll
        for (int ks = 0; ks < 4; ks++) {
            uint32_t afr[4][4];
            #pragma unroll
            for (int mf = 0; mf < 4; mf++) {
                int rr  = mf * 16 + ((g & 1) << 3) + r8;
                int c16 = kit * 8 + 2 * ks + (g >> 1);
                ldsm_x4(afr[mf][0], afr[mf][1], afr[mf][2], afr[mf][3],
                        sbase + P1_SM_A + SWA(rr, c16));
            }
            uint32_t bfr[2][4];
            #pragma unroll
            for (int nf2 = 0; nf2 < 2; nf2++) {
                int rr = warp_n * 32 + nf2 * 16 + ((g >> 1) << 3) + r8;
                int ch = 2 * ks + (g & 1);
                ldsm_x4(bfr[nf2][0], bfr[nf2][1], bfr[nf2][2], bfr[nf2][3],
                        Bbase + SWB(rr, ch));
            }
            #pragma unroll
            for (int mf = 0; mf < 4; mf++)
                #pragma unroll
                for (int nf = 0; nf < 4; nf++)
                    mma_bf16(acc[mf][nf], afr[mf],
                             bfr[nf >> 1][(nf & 1) * 2], bfr[nf >> 1][(nf & 1) * 2 + 1]);
        }

        if (kit == 7) {   // tile done: fold approx scores into per-owner top-2
            #pragma unroll
            for (int nf = 0; nf < 4; nf++) {
                const int code0 = code_base + nt * 128 + warp_n * 32 + nf * 8 + (lane & 3) * 2;
                const float c2a = __ldg(&g_c2[code0]);
                const float c2b = __ldg(&g_c2[code0 + 1]);
                #pragma unroll
                for (int mf = 0; mf < 4; mf++)
                    #pragma unroll
                    for (int h = 0; h < 2; h++) {
                        const int ridx = mf * 2 + h;
                        float v0 = c2a - 2.0f * acc[mf][nf][h * 2 + 0];
                        float v1 = c2b - 2.0f * acc[mf][nf][h * 2 + 1];
                        TOP2(v0, code0,     ridx);
                        TOP2(v1, code0 + 1, ridx);
                    }
            }
        }
    }
    #undef P1_ISSUE
    #undef TOP2

    // store per-owner top-2: one uint4 per (xblk,row,slot)
    const int slot = warp_n * 4 + (lane & 3);
    #pragma unroll
    for (int ridx = 0; ridx < 8; ridx++) {
        const int mf = ridx >> 1, h = ridx & 1;
        const int row = row0 + mf * 16 + h * 8 + (lane >> 2);
        uint4 v;
        v.x = __float_as_uint(tv1[ridx]); v.y = (uint32_t)ti1[ridx];
        v.z = __float_as_uint(tv2[ridx]); v.w = (uint32_t)ti2[ridx];
        g_top[((size_t)blockIdx.x * B_ + row) * 16 + slot] = v;
    }
}

// ---------------------------------------------------------------------------
// Phase 2 (fused with output): read 128 owners/row from g_top, gmin over v1,
// candidates = any v1/v2 < gmin+margin, exact fp64 rescore (reference-grid
// fp32 rounding + index tie-break), then write z_q_st row, index, vq_loss.
// 1 warp per row; lane handles 4 owners.
// ---------------------------------------------------------------------------
__global__ __launch_bounds__(256) void phase2_kernel(const float* __restrict__ cb,
                                                     float* __restrict__ out) {
    __shared__ int s_cnt[8];
    __shared__ int s_list[8][CAP];
    const int wid  = threadIdx.x >> 5;
    const int lane = threadIdx.x & 31;
    const int row  = blockIdx.x * 8 + wid;

    uint4 own[4];
    float gmin = 3.4e38f;
    #pragma unroll
    for (int j = 0; j < 4; j++) {
        const int o = lane * 4 + j;
        const int xblk = o >> 4, slot = o & 15;
        own[j] = g_top[((size_t)xblk * B_ + row) * 16 + slot];
        gmin = fminf(gmin, __uint_as_float(own[j].x));
    }
    #pragma unroll
    for (int o = 16; o; o >>= 1) gmin = fminf(gmin, __shfl_xor_sync(0xffffffffu, gmin, o));
    const float thr = gmin + MARGIN2;

    if (lane == 0) s_cnt[wid] = 0;
    __syncwarp();
    #pragma unroll
    for (int j = 0; j < 4; j++) {
        if (__uint_as_float(own[j].x) < thr) {
            int p = atomicAdd(&s_cnt[wid], 1); if (p < CAP) s_list[wid][p] = (int)own[j].y;
        }
        if (__uint_as_float(own[j].z) < thr) {
            int p = atomicAdd(&s_cnt[wid], 1); if (p < CAP) s_list[wid][p] = (int)own[j].w;
        }
    }
    __syncwarp();
    const int ncand = s_cnt[wid];

    const float* ze = g_ze + (size_t)row * D_;
    const float  zz = g_zz[row];
    float bv = 3.4e38f;
    int   bi = 0x7fffffff;

    if (ncand <= CAP) {
        for (int c = 0; c < ncand; c++) {
            const int k = s_list[wid][c];
            const float* cr = cb + (size_t)k * D_;
            double d = 0.0;
            #pragma unroll
            for (int j = 0; j < 16; j++) {
                int dd = lane + j * 32;
                d = fma((double)ze[dd], (double)cr[dd], d);
            }
            #pragma unroll
            for (int o = 16; o; o >>= 1) d += __shfl_xor_sync(0xffffffffu, d, o);
            float t = __fadd_rn(zz, -2.0f * (float)d);
            float v = __fadd_rn(t, g_c2[k]);
            if (v < bv || (v == bv && k < bi)) { bv = v; bi = k; }
        }
    } else {
        // pathological fallback: full exact scan
        for (int k = 0; k < K_; k++) {
            const float* cr = cb + (size_t)k * D_;
            double d = 0.0;
            #pragma unroll
            for (int j = 0; j < 16; j++) {
                int dd = lane + j * 32;
                d = fma((double)ze[dd], (double)cr[dd], d);
            }
            #pragma unroll
            for (int o = 16; o; o >>= 1) d += __shfl_xor_sync(0xffffffffu, d, o);
            float t = __fadd_rn(zz, -2.0f * (float)d);
            float v = __fadd_rn(t, g_c2[k]);
            if (v < bv || (v == bv && k < bi)) { bv = v; bi = k; }
        }
    }
    bi = __shfl_sync(0xffffffffu, bi, 0);

    // fused output: z_q_st row + loss + index
    const float* zq = cb + (size_t)bi * D_;
    float* o = out + (size_t)row * D_;
    float s = 0.f;
    #pragma unroll
    for (int j = 0; j < 16; j++) {
        const int d = lane + j * 32;
        float e    = ze[d];
        float q    = zq[d];
        float diff = q - e;
        o[d] = e + diff;
        s += diff * diff;
    }
    #pragma unroll
    for (int off = 16; off; off >>= 1) s += __shfl_xor_sync(0xffffffffu, s, off);
    if (lane == 0) {
        g_idx[row] = bi;
        out[(size_t)B_ * D_ + row]      = (float)bi;
        out[(size_t)B_ * D_ + B_ + row] = s / (float)D_;
    }
}

// ---------------------------------------------------------------------------
extern "C" void kernel_launch(void* const* d_in, const int* in_sizes, int n_in,
                              void* d_out, int out_size) {
    const float* x  = (const float*)d_in[0];
    const float* W  = (const float*)d_in[1];
    const float* cb = (const float*)d_in[2];
    float* out = (float*)d_out;
    (void)in_sizes; (void)n_in; (void)out_size;

    cudaFuncSetAttribute(gemm1_mma_kernel, cudaFuncAttributeMaxDynamicSharedMemorySize, SM1TOT);
    cudaFuncSetAttribute(phase1_kernel,    cudaFuncAttributeMaxDynamicSharedMemorySize, P1_SMTOT);

    pack_x_kernel<<<B_, 256>>>(x);
    pack_w_kernel<<<D_, 256>>>(W);
    cbprep_kernel<<<K_ / 8, 256>>>(cb);
    gemm1_mma_kernel<<<dim3(4, 256), 128, SM1TOT>>>();
    zz_kernel<<<B_ / 8, 256>>>();
    phase1_kernel<<<dim3(8, 256), 128, P1_SMTOT>>>();
    phase2_kernel<<<B_ / 8, 256>>>(cb, out);
}

// round 12
// speedup vs baseline: 1.3182x; 1.0364x over previous
#include <cuda_runtime.h>
#include <cuda_bf16.h>
#include <cuda_fp16.h>
#include <cstdint>

// Problem constants
#define B_   16384
#define DIN  1024
#define D_   512
#define K_   8192
#define KP2  3072          // gemm1 packed K: [a0|a0|a1] . [b0|b1|b0]

#define MARGIN2 0.08f      // bf16 approx-score collect margin (2-sided 7sigma)
#define CAP     32

// ---------------------------------------------------------------------------
// Scratch (device globals; allocations forbidden)
// ---------------------------------------------------------------------------
__device__ float  g_ze[(size_t)B_ * D_];     // z_e fp32
__device__ float  g_c2[K_];
__device__ int    g_idx[B_];
__device__ uint4  g_top[(size_t)8 * B_ * 16];      // per-(xblk,row,slot) top-2, 32MB
__device__ __nv_bfloat16 g_xs[(size_t)B_ * KP2];   // packed x splits
__device__ __nv_bfloat16 g_ws[(size_t)D_ * KP2];   // packed W splits
__device__ __nv_bfloat16 g_zb[(size_t)B_ * D_];    // bf16(z_e)
__device__ __nv_bfloat16 g_cbb[(size_t)K_ * D_];   // bf16(cb)

// ---------------------------------------------------------------------------
// PTX helpers (baseline PTX only: works at .target sm_100)
// ---------------------------------------------------------------------------
__device__ __forceinline__ uint32_t smem_u32(const void* p) {
    uint32_t a;
    asm("{ .reg .u64 t; cvta.to.shared.u64 t, %1; cvt.u32.u64 %0, t; }" : "=r"(a) : "l"(p));
    return a;
}
__device__ __forceinline__ void cp_async16(uint32_t saddr, const void* gaddr) {
    asm volatile("cp.async.cg.shared.global [%0], [%1], 16;" :: "r"(saddr), "l"(gaddr));
}
__device__ __forceinline__ void cp_commit() { asm volatile("cp.async.commit_group;"); }
__device__ __forceinline__ void cp_wait1()  { asm volatile("cp.async.wait_group 1;" ::: "memory"); }

__device__ __forceinline__ void ldsm_x4(uint32_t& r0, uint32_t& r1, uint32_t& r2, uint32_t& r3,
                                        uint32_t addr) {
    asm volatile("ldmatrix.sync.aligned.m8n8.x4.shared.b16 {%0,%1,%2,%3}, [%4];"
                 : "=r"(r0), "=r"(r1), "=r"(r2), "=r"(r3) : "r"(addr));
}
__device__ __forceinline__ void mma_bf16(float* c, const uint32_t* a, uint32_t b0, uint32_t b1) {
    asm volatile("mma.sync.aligned.m16n8k16.row.col.f32.bf16.bf16.f32 "
                 "{%0,%1,%2,%3}, {%4,%5,%6,%7}, {%8,%9}, {%0,%1,%2,%3};"
                 : "+f"(c[0]), "+f"(c[1]), "+f"(c[2]), "+f"(c[3])
                 : "r"(a[0]), "r"(a[1]), "r"(a[2]), "r"(a[3]), "r"(b0), "r"(b1));
}

// Swizzles:
// A-resident (phase1): 1024B rows, 64 x 16B chunks, XOR within 8-chunk groups
#define SWA(r, c) ((r) * 1024 + ((((c) & 0x38) | (((c) & 7) ^ ((r) & 7))) << 4))
// 128B-row stage tiles (BLK_K=64 bf16): 8 x 16B chunks, XOR by row
#define SWB(r, c) ((r) * 128 + ((((c) ^ ((r) & 7)) & 7) << 4))

// ---------------------------------------------------------------------------
// Codebook prep: c2 + bf16 pack, single 16MB read. 1 warp per code row.
// ---------------------------------------------------------------------------
__global__ void cbprep_kernel(const float* __restrict__ cb) {
    const int row  = blockIdx.x * 8 + (threadIdx.x >> 5);
    const int lane = threadIdx.x & 31;
    const float4* src = reinterpret_cast<const float4*>(cb + (size_t)row * D_);
    __nv_bfloat162* dst = reinterpret_cast<__nv_bfloat162*>(g_cbb + (size_t)row * D_);
    float s = 0.f;
    #pragma unroll
    for (int j = 0; j < 4; j++) {
        const int i = lane + j * 32;
        float4 v = src[i];
        s += v.x * v.x + v.y * v.y + v.z * v.z + v.w * v.w;
        __nv_bfloat162 h0, h1;
        h0.x = __float2bfloat16_rn(v.x); h0.y = __float2bfloat16_rn(v.y);
        h1.x = __float2bfloat16_rn(v.z); h1.y = __float2bfloat16_rn(v.w);
        dst[i * 2]     = h0;
        dst[i * 2 + 1] = h1;
    }
    #pragma unroll
    for (int o = 16; o; o >>= 1) s += __shfl_xor_sync(0xffffffffu, s, o);
    if (lane == 0) g_c2[row] = s;
}

// ---------------------------------------------------------------------------
// Merged pack kernel for gemm1 operands (bf16 3-split).
// Blocks [0, B_) pack x rows; blocks [B_, B_+D_) pack W rows.
// ---------------------------------------------------------------------------
__global__ void pack_xw_kernel(const float* __restrict__ x, const float* __restrict__ w) {
    const int b = blockIdx.x, t = threadIdx.x;
    const bool isx = (b < B_);
    const int row = isx ? b : (b - B_);
    const float* src = isx ? x : w;

    float4 v = *reinterpret_cast<const float4*>(src + (size_t)row * DIN + t * 4);
    __nv_bfloat162 h01, h23, l01, l23;
    h01.x = __float2bfloat16_rn(v.x); h01.y = __float2bfloat16_rn(v.y);
    h23.x = __float2bfloat16_rn(v.z); h23.y = __float2bfloat16_rn(v.w);
    l01.x = __float2bfloat16_rn(v.x - __bfloat162float(h01.x));
    l01.y = __float2bfloat16_rn(v.y - __bfloat162float(h01.y));
    l23.x = __float2bfloat16_rn(v.z - __bfloat162float(h23.x));
    l23.y = __float2bfloat16_rn(v.w - __bfloat162float(h23.y));

    if (isx) {
        // x: [a0 | a0 | a1]
        __nv_bfloat162* d = reinterpret_cast<__nv_bfloat162*>(g_xs + (size_t)row * KP2 + t * 4);
        d[0] = h01; d[1] = h23;
        d += 512;  d[0] = h01; d[1] = h23;
        d += 512;  d[0] = l01; d[1] = l23;
    } else {
        // W: [b0 | b1 | b0]
        __nv_bfloat162* d = reinterpret_cast<__nv_bfloat162*>(g_ws + (size_t)row * KP2 + t * 4);
        d[0] = h01; d[1] = h23;
        d += 512;  d[0] = l01; d[1] = l23;
        d += 512;  d[0] = h01; d[1] = h23;
    }
}

// ---------------------------------------------------------------------------
// GEMM1 via mma.sync: z_e = x @ W^T with packed 3-split (K''=3072).
// 128-thread CTAs, M-tile 64, 2 CTAs/SM. BLK_K=64, 3-stage cp.async.
// grid (4, 256). Epilogue also emits bf16(z_e).
// ---------------------------------------------------------------------------
#define G1_SA   8192                 // A stage bytes (64 x 128B)
#define G1_SB   16384                // B stage bytes (128 x 128B)
#define G1_BOFF (3 * G1_SA)          // 24576
#define SM1TOT  (3 * G1_SA + 3 * G1_SB)   // 73728 per CTA

__global__ __launch_bounds__(128, 2) void gemm1_mma_kernel() {
    extern __shared__ char sm[];
    const uint32_t sbase = smem_u32(sm);
    const int tid  = threadIdx.x;
    const int lane = tid & 31;
    const int warp_n = tid >> 5;       // 0..3
    const int row0 = blockIdx.y * 64;
    const int col0 = blockIdx.x * 128;
    const int NKIT = KP2 / 64;         // 48

    const __nv_bfloat16* gA = g_xs + (size_t)row0 * KP2;
    const __nv_bfloat16* gB = g_ws + (size_t)col0 * KP2;

    float acc[4][4][4];
    #pragma unroll
    for (int mf = 0; mf < 4; mf++)
        #pragma unroll
        for (int nf = 0; nf < 4; nf++)
            #pragma unroll
            for (int q = 0; q < 4; q++) acc[mf][nf][q] = 0.f;

    #define G1_ISSUE(stg, kit) do {                                               \
        const uint32_t As_ = sbase + (stg) * G1_SA;                               \
        const uint32_t Bs_ = sbase + G1_BOFF + (stg) * G1_SB;                     \
        const int koff_ = (kit) * 64;                                             \
        _Pragma("unroll")                                                          \
        for (int i_ = 0; i_ < 4; i_++) {                                           \
            int id_ = tid + i_ * 128;                                              \
            int r_  = id_ >> 3;                                                    \
            int c_  = id_ & 7;                                                     \
            cp_async16(As_ + SWB(r_, c_), gA + (size_t)r_ * KP2 + koff_ + c_ * 8); \
        }                                                                          \
        _Pragma("unroll")                                                          \
        for (int i_ = 0; i_ < 8; i_++) {                                           \
            int id_ = tid + i_ * 128;                                              \
            int r_  = id_ >> 3;                                                    \
            int c_  = id_ & 7;                                                     \
            cp_async16(Bs_ + SWB(r_, c_), gB + (size_t)r_ * KP2 + koff_ + c_ * 8); \
        }                                                                          \
    } while (0)

    G1_ISSUE(0, 0); cp_commit();
    G1_ISSUE(1, 1); cp_commit();

    const int g = lane >> 3;
    const int r8 = lane & 7;

    for (int kit = 0; kit < NKIT; kit++) {
        cp_wait1();
        __syncthreads();
        if (kit + 2 < NKIT) G1_ISSUE((kit + 2) % 3, kit + 2);
        cp_commit();

        const int stg = kit % 3;
        const uint32_t Abase = sbase + stg * G1_SA;
        const uint32_t Bbase = sbase + G1_BOFF + stg * G1_SB;

        #pragma unroll
        for (int ks = 0; ks < 4; ks++) {
            uint32_t afr[4][4];
            #pragma unroll
            for (int mf = 0; mf < 4; mf++) {
                int rr = mf * 16 + ((g & 1) << 3) + r8;
                int ch = 2 * ks + (g >> 1);
                ldsm_x4(afr[mf][0], afr[mf][1], afr[mf][2], afr[mf][3],
                        Abase + SWB(rr, ch));
            }
            uint32_t bfr[2][4];
            #pragma unroll
            for (int nf2 = 0; nf2 < 2; nf2++) {
                int rr = warp_n * 32 + nf2 * 16 + ((g >> 1) << 3) + r8;
                int ch = 2 * ks + (g & 1);
                ldsm_x4(bfr[nf2][0], bfr[nf2][1], bfr[nf2][2], bfr[nf2][3],
                        Bbase + SWB(rr, ch));
            }
            #pragma unroll
            for (int mf = 0; mf < 4; mf++)
                #pragma unroll
                for (int nf = 0; nf < 4; nf++)
                    mma_bf16(acc[mf][nf], afr[mf],
                             bfr[nf >> 1][(nf & 1) * 2], bfr[nf >> 1][(nf & 1) * 2 + 1]);
        }
    }
    #undef G1_ISSUE

    #pragma unroll
    for (int mf = 0; mf < 4; mf++)
        #pragma unroll
        for (int h = 0; h < 2; h++) {
            const int row = row0 + mf * 16 + h * 8 + (lane >> 2);
            #pragma unroll
            for (int nf = 0; nf < 4; nf++) {
                const int col = col0 + warp_n * 32 + nf * 8 + (lane & 3) * 2;
                float2 o; o.x = acc[mf][nf][h * 2]; o.y = acc[mf][nf][h * 2 + 1];
                *reinterpret_cast<float2*>(g_ze + (size_t)row * D_ + col) = o;
                __nv_bfloat162 hb;
                hb.x = __float2bfloat16_rn(o.x); hb.y = __float2bfloat16_rn(o.y);
                *reinterpret_cast<__nv_bfloat162*>(g_zb + (size_t)row * D_ + col) = hb;
            }
        }
}

// ---------------------------------------------------------------------------
// Phase 1: single-pass bf16 approx GEMM with BRANCHLESS per-owner top-2.
// 128-thread CTAs, M-tile 64, 2 CTAs/SM. A resident (64KB), B streamed
// 16KB x 3. Each (thread,row-slot) owner keeps (v1,i1,v2,i2) over its
// 128 codes; stored as one uint4 per owner -> g_top (32MB total).
// grid (8, 256).
// ---------------------------------------------------------------------------
#define P1_SM_A  0
#define P1_SM_B  65536
#define P1_SB    16384
#define P1_SMTOT (65536 + 3 * P1_SB)   // 114688 per CTA -> 2/SM

__global__ __launch_bounds__(128, 2) void phase1_kernel() {
    extern __shared__ char sm[];
    const uint32_t sbase = smem_u32(sm);
    const int tid  = threadIdx.x;
    const int lane = tid & 31;
    const int warp_n = tid >> 5;       // 0..3
    const int row0 = blockIdx.y * 64;
    const int code_base = blockIdx.x * 1024;

    // resident A: 64 rows x 64 chunks(16B)
    {
        const __nv_bfloat16* gA = g_zb + (size_t)row0 * D_;
        #pragma unroll
        for (int i = 0; i < 32; i++) {
            int idx = tid + i * 128;
            int r   = idx >> 6;
            int c16 = idx & 63;
            cp_async16(sbase + P1_SM_A + SWA(r, c16), gA + (size_t)r * D_ + c16 * 8);
        }
    }
    cp_commit();

    #define P1_ISSUE(stg, u) do {                                                  \
        const uint32_t Bs_ = sbase + P1_SM_B + (stg) * P1_SB;                      \
        const int nt_ = (u) >> 3, kit_ = (u) & 7;                                  \
        const __nv_bfloat16* gB_ = g_cbb + (size_t)(code_base + nt_ * 128) * D_;   \
        _Pragma("unroll")                                                          \
        for (int i_ = 0; i_ < 8; i_++) {                                           \
            int id_ = tid + i_ * 128;                                              \
            int r_  = id_ >> 3;                                                    \
            int c_  = id_ & 7;                                                     \
            cp_async16(Bs_ + SWB(r_, c_),                                          \
                       gB_ + (size_t)r_ * D_ + kit_ * 64 + c_ * 8);                \
        }                                                                          \
    } while (0)

    P1_ISSUE(0, 0); cp_commit();
    P1_ISSUE(1, 1); cp_commit();

    const int g = lane >> 3;
    const int r8 = lane & 7;
    float acc[4][4][4];

    // per-owner top-2 (8 row-slots per thread), branchless updates only
    float tv1[8], tv2[8];
    int   ti1[8], ti2[8];
    #pragma unroll
    for (int i = 0; i < 8; i++) {
        tv1[i] = 3.4e38f; tv2[i] = 3.4e38f;
        ti1[i] = 0x7fffffff; ti2[i] = 0x7fffffff;
    }

    #define TOP2(v, k, r) do {                                                     \
        const bool l1_ = (v) < tv1[r];                                             \
        const bool l2_ = (v) < tv2[r];                                             \
        const float nv2_ = l1_ ? tv1[r] : (l2_ ? (v) : tv2[r]);                    \
        const int   ni2_ = l1_ ? ti1[r] : (l2_ ? (k) : ti2[r]);                    \
        tv1[r] = l1_ ? (v) : tv1[r];                                               \
        ti1[r] = l1_ ? (k) : ti1[r];                                               \
        tv2[r] = nv2_; ti2[r] = ni2_;                                              \
    } while (0)

    for (int u = 0; u < 64; u++) {
        const int nt = u >> 3, kit = u & 7;
        cp_wait1();
        __syncthreads();
        if (u + 2 < 64) P1_ISSUE((u + 2) % 3, u + 2);
        cp_commit();

        if (kit == 0) {
            #pragma unroll
            for (int mf = 0; mf < 4; mf++)
                #pragma unroll
                for (int nf = 0; nf < 4; nf++)
                    #pragma unroll
                    for (int q = 0; q < 4; q++) acc[mf][nf][q] = 0.f;
        }

        const uint32_t Bbase = sbase + P1_SM_B + (u % 3) * P1_SB;
        #pragma unroll
        for (int ks = 0; ks < 4; ks++) {
            uint32_t afr[4][4];
            #pragma unroll
            for (int mf = 0; mf < 4; mf++) {
                int rr  = mf * 16 + ((g & 1) << 3) + r8;
                int c16 = kit * 8 + 2 * ks + (g >> 1);
                ldsm_x4(afr[mf][0], afr[mf][1], afr[mf][2], afr[mf][3],
                        sbase + P1_SM_A + SWA(rr, c16));
            }
            uint32_t bfr[2][4];
            #pragma unroll
            for (int nf2 = 0; nf2 < 2; nf2++) {
                int rr = warp_n * 32 + nf2 * 16 + ((g >> 1) << 3) + r8;
                int ch = 2 * ks + (g & 1);
                ldsm_x4(bfr[nf2][0], bfr[nf2][1], bfr[nf2][2], bfr[nf2][3],
                        Bbase + SWB(rr, ch));
            }
            #pragma unroll
            for (int mf = 0; mf < 4; mf++)
                #pragma unroll
                for (int nf = 0; nf < 4; nf++)
                    mma_bf16(acc[mf][nf], afr[mf],
                             bfr[nf >> 1][(nf & 1) * 2], bfr[nf >> 1][(nf & 1) * 2 + 1]);
        }

        if (kit == 7) {   // tile done: fold approx scores into per-owner top-2
            #pragma unroll
            for (int nf = 0; nf < 4; nf++) {
                const int code0 = code_base + nt * 128 + warp_n * 32 + nf * 8 + (lane & 3) * 2;
                const float c2a = __ldg(&g_c2[code0]);
                const float c2b = __ldg(&g_c2[code0 + 1]);
                #pragma unroll
                for (int mf = 0; mf < 4; mf++)
                    #pragma unroll
                    for (int h = 0; h < 2; h++) {
                        const int ridx = mf * 2 + h;
                        float v0 = c2a - 2.0f * acc[mf][nf][h * 2 + 0];
                        float v1 = c2b - 2.0f * acc[mf][nf][h * 2 + 1];
                        TOP2(v0, code0,     ridx);
                        TOP2(v1, code0 + 1, ridx);
                    }
            }
        }
    }
    #undef P1_ISSUE
    #undef TOP2

    // store per-owner top-2: one uint4 per (xblk,row,slot)
    const int slot = warp_n * 4 + (lane & 3);
    #pragma unroll
    for (int ridx = 0; ridx < 8; ridx++) {
        const int mf = ridx >> 1, h = ridx & 1;
        const int row = row0 + mf * 16 + h * 8 + (lane >> 2);
        uint4 v;
        v.x = __float_as_uint(tv1[ridx]); v.y = (uint32_t)ti1[ridx];
        v.z = __float_as_uint(tv2[ridx]); v.w = (uint32_t)ti2[ridx];
        g_top[((size_t)blockIdx.x * B_ + row) * 16 + slot] = v;
    }
}

// ---------------------------------------------------------------------------
// Phase 2 (fused with zz + output): read 128 owners/row from g_top, gmin over
// v1, candidates = any v1/v2 < gmin+margin; ze row cached in registers; zz
// computed in fp64 with the same reduction order as the old zz_kernel; exact
// fp64 rescore (reference-grid fp32 rounding + index tie-break); writes
// z_q_st row, index, vq_loss. 1 warp per row.
// ---------------------------------------------------------------------------
__global__ __launch_bounds__(256) void phase2_kernel(const float* __restrict__ cb,
                                                     float* __restrict__ out) {
    __shared__ int s_cnt[8];
    __shared__ int s_list[8][CAP];
    const int wid  = threadIdx.x >> 5;
    const int lane = threadIdx.x & 31;
    const int row  = blockIdx.x * 8 + wid;

    // cache ze row in registers + fp64 zz (bit-identical order to old zz_kernel)
    const float* ze = g_ze + (size_t)row * D_;
    float er[16];
    double zs = 0.0;
    #pragma unroll
    for (int j = 0; j < 16; j++) {
        er[j] = ze[lane + j * 32];
        double v = (double)er[j];
        zs += v * v;
    }
    #pragma unroll
    for (int o = 16; o; o >>= 1) zs += __shfl_xor_sync(0xffffffffu, zs, o);
    const float zz = (float)zs;

    uint4 own[4];
    float gmin = 3.4e38f;
    #pragma unroll
    for (int j = 0; j < 4; j++) {
        const int o = lane * 4 + j;
        const int xblk = o >> 4, slot = o & 15;
        own[j] = g_top[((size_t)xblk * B_ + row) * 16 + slot];
        gmin = fminf(gmin, __uint_as_float(own[j].x));
    }
    #pragma unroll
    for (int o = 16; o; o >>= 1) gmin = fminf(gmin, __shfl_xor_sync(0xffffffffu, gmin, o));
    const float thr = gmin + MARGIN2;

    if (lane == 0) s_cnt[wid] = 0;
    __syncwarp();
    #pragma unroll
    for (int j = 0; j < 4; j++) {
        if (__uint_as_float(own[j].x) < thr) {
            int p = atomicAdd(&s_cnt[wid], 1); if (p < CAP) s_list[wid][p] = (int)own[j].y;
        }
        if (__uint_as_float(own[j].z) < thr) {
            int p = atomicAdd(&s_cnt[wid], 1); if (p < CAP) s_list[wid][p] = (int)own[j].w;
        }
    }
    __syncwarp();
    const int ncand = s_cnt[wid];

    float bv = 3.4e38f;
    int   bi = 0x7fffffff;

    if (ncand <= CAP) {
        for (int c = 0; c < ncand; c++) {
            const int k = s_list[wid][c];
            const float* cr = cb + (size_t)k * D_;
            double d = 0.0;
            #pragma unroll
            for (int j = 0; j < 16; j++)
                d = fma((double)er[j], (double)cr[lane + j * 32], d);
            #pragma unroll
            for (int o = 16; o; o >>= 1) d += __shfl_xor_sync(0xffffffffu, d, o);
            float t = __fadd_rn(zz, -2.0f * (float)d);
            float v = __fadd_rn(t, g_c2[k]);
            if (v < bv || (v == bv && k < bi)) { bv = v; bi = k; }
        }
    } else {
        // pathological fallback: full exact scan
        for (int k = 0; k < K_; k++) {
            const float* cr = cb + (size_t)k * D_;
            double d = 0.0;
            #pragma unroll
            for (int j = 0; j < 16; j++)
                d = fma((double)er[j], (double)cr[lane + j * 32], d);
            #pragma unroll
            for (int o = 16; o; o >>= 1) d += __shfl_xor_sync(0xffffffffu, d, o);
            float t = __fadd_rn(zz, -2.0f * (float)d);
            float v = __fadd_rn(t, g_c2[k]);
            if (v < bv || (v == bv && k < bi)) { bv = v; bi = k; }
        }
    }
    bi = __shfl_sync(0xffffffffu, bi, 0);

    // fused output: z_q_st row + loss + index (ze from registers)
    const float* zq = cb + (size_t)bi * D_;
    float* o = out + (size_t)row * D_;
    float s = 0.f;
    #pragma unroll
    for (int j = 0; j < 16; j++) {
        const int d = lane + j * 32;
        float e    = er[j];
        float q    = zq[d];
        float diff = q - e;
        o[d] = e + diff;
        s += diff * diff;
    }
    #pragma unroll
    for (int off = 16; off; off >>= 1) s += __shfl_xor_sync(0xffffffffu, s, off);
    if (lane == 0) {
        g_idx[row] = bi;
        out[(size_t)B_ * D_ + row]      = (float)bi;
        out[(size_t)B_ * D_ + B_ + row] = s / (float)D_;
    }
}

// ---------------------------------------------------------------------------
extern "C" void kernel_launch(void* const* d_in, const int* in_sizes, int n_in,
                              void* d_out, int out_size) {
    const float* x  = (const float*)d_in[0];
    const float* W  = (const float*)d_in[1];
    const float* cb = (const float*)d_in[2];
    float* out = (float*)d_out;
    (void)in_sizes; (void)n_in; (void)out_size;

    cudaFuncSetAttribute(gemm1_mma_kernel, cudaFuncAttributeMaxDynamicSharedMemorySize, SM1TOT);
    cudaFuncSetAttribute(phase1_kernel,    cudaFuncAttributeMaxDynamicSharedMemorySize, P1_SMTOT);

    pack_xw_kernel<<<B_ + D_, 256>>>(x, W);
    cbprep_kernel<<<K_ / 8, 256>>>(cb);
    gemm1_mma_kernel<<<dim3(4, 256), 128, SM1TOT>>>();
    phase1_kernel<<<dim3(8, 256), 128, P1_SMTOT>>>();
    phase2_kernel<<<B_ / 8, 256>>>(cb, out);
}

// round 13
// speedup vs baseline: 1.3438x; 1.0194x over previous
#include <cuda_runtime.h>
#include <cuda_bf16.h>
#include <cuda_fp16.h>
#include <cstdint>

// Problem constants
#define B_   16384
#define DIN  1024
#define D_   512
#define K_   8192
#define KP2  3072          // gemm1 packed K: [a0|a0|a1] . [b0|b1|b0]

#define MARGIN2 0.12f      // bf16 noise (0.08) + packed-score quantization slack
#define CAP     32

// ---------------------------------------------------------------------------
// Scratch (device globals; allocations forbidden)
// ---------------------------------------------------------------------------
__device__ float  g_ze[(size_t)B_ * D_];     // z_e fp32
__device__ float  g_c2[K_];                  // |c|^2 (exact, for rescore)
__device__ float  g_c2b[K_];                 // |c|^2 + 16 (biased, for phase1)
__device__ int    g_idx[B_];
__device__ uint2  g_top[(size_t)8 * B_ * 16];      // per-(xblk,row,slot) packed top-2, 16MB
__device__ __nv_bfloat16 g_xs[(size_t)B_ * KP2];   // packed x splits
__device__ __nv_bfloat16 g_ws[(size_t)D_ * KP2];   // packed W splits
__device__ __nv_bfloat16 g_zb[(size_t)B_ * D_];    // bf16(z_e)
__device__ __nv_bfloat16 g_cbb[(size_t)K_ * D_];   // bf16(cb)

// ---------------------------------------------------------------------------
// PTX helpers (baseline PTX only: works at .target sm_100)
// ---------------------------------------------------------------------------
__device__ __forceinline__ uint32_t smem_u32(const void* p) {
    uint32_t a;
    asm("{ .reg .u64 t; cvta.to.shared.u64 t, %1; cvt.u32.u64 %0, t; }" : "=r"(a) : "l"(p));
    return a;
}
__device__ __forceinline__ void cp_async16(uint32_t saddr, const void* gaddr) {
    asm volatile("cp.async.cg.shared.global [%0], [%1], 16;" :: "r"(saddr), "l"(gaddr));
}
__device__ __forceinline__ void cp_commit() { asm volatile("cp.async.commit_group;"); }
__device__ __forceinline__ void cp_wait1()  { asm volatile("cp.async.wait_group 1;" ::: "memory"); }

__device__ __forceinline__ void ldsm_x4(uint32_t& r0, uint32_t& r1, uint32_t& r2, uint32_t& r3,
                                        uint32_t addr) {
    asm volatile("ldmatrix.sync.aligned.m8n8.x4.shared.b16 {%0,%1,%2,%3}, [%4];"
                 : "=r"(r0), "=r"(r1), "=r"(r2), "=r"(r3) : "r"(addr));
}
__device__ __forceinline__ void mma_bf16(float* c, const uint32_t* a, uint32_t b0, uint32_t b1) {
    asm volatile("mma.sync.aligned.m16n8k16.row.col.f32.bf16.bf16.f32 "
                 "{%0,%1,%2,%3}, {%4,%5,%6,%7}, {%8,%9}, {%0,%1,%2,%3};"
                 : "+f"(c[0]), "+f"(c[1]), "+f"(c[2]), "+f"(c[3])
                 : "r"(a[0]), "r"(a[1]), "r"(a[2]), "r"(a[3]), "r"(b0), "r"(b1));
}

// Swizzles:
// A-resident (phase1): 1024B rows, 64 x 16B chunks, XOR within 8-chunk groups
#define SWA(r, c) ((r) * 1024 + ((((c) & 0x38) | (((c) & 7) ^ ((r) & 7))) << 4))
// 128B-row stage tiles (BLK_K=64 bf16): 8 x 16B chunks, XOR by row
#define SWB(r, c) ((r) * 128 + ((((c) ^ ((r) & 7)) & 7) << 4))

// ---------------------------------------------------------------------------
// Codebook prep: c2 (exact + biased) + bf16 pack, single 16MB read.
// ---------------------------------------------------------------------------
__global__ void cbprep_kernel(const float* __restrict__ cb) {
    const int row  = blockIdx.x * 8 + (threadIdx.x >> 5);
    const int lane = threadIdx.x & 31;
    const float4* src = reinterpret_cast<const float4*>(cb + (size_t)row * D_);
    __nv_bfloat162* dst = reinterpret_cast<__nv_bfloat162*>(g_cbb + (size_t)row * D_);
    float s = 0.f;
    #pragma unroll
    for (int j = 0; j < 4; j++) {
        const int i = lane + j * 32;
        float4 v = src[i];
        s += v.x * v.x + v.y * v.y + v.z * v.z + v.w * v.w;
        __nv_bfloat162 h0, h1;
        h0.x = __float2bfloat16_rn(v.x); h0.y = __float2bfloat16_rn(v.y);
        h1.x = __float2bfloat16_rn(v.z); h1.y = __float2bfloat16_rn(v.w);
        dst[i * 2]     = h0;
        dst[i * 2 + 1] = h1;
    }
    #pragma unroll
    for (int o = 16; o; o >>= 1) s += __shfl_xor_sync(0xffffffffu, s, o);
    if (lane == 0) { g_c2[row] = s; g_c2b[row] = s + 16.0f; }
}

// ---------------------------------------------------------------------------
// Merged pack kernel for gemm1 operands (bf16 3-split).
// Blocks [0, B_) pack x rows; blocks [B_, B_+D_) pack W rows.
// ---------------------------------------------------------------------------
__global__ void pack_xw_kernel(const float* __restrict__ x, const float* __restrict__ w) {
    const int b = blockIdx.x, t = threadIdx.x;
    const bool isx = (b < B_);
    const int row = isx ? b : (b - B_);
    const float* src = isx ? x : w;

    float4 v = *reinterpret_cast<const float4*>(src + (size_t)row * DIN + t * 4);
    __nv_bfloat162 h01, h23, l01, l23;
    h01.x = __float2bfloat16_rn(v.x); h01.y = __float2bfloat16_rn(v.y);
    h23.x = __float2bfloat16_rn(v.z); h23.y = __float2bfloat16_rn(v.w);
    l01.x = __float2bfloat16_rn(v.x - __bfloat162float(h01.x));
    l01.y = __float2bfloat16_rn(v.y - __bfloat162float(h01.y));
    l23.x = __float2bfloat16_rn(v.z - __bfloat162float(h23.x));
    l23.y = __float2bfloat16_rn(v.w - __bfloat162float(h23.y));

    if (isx) {
        __nv_bfloat162* d = reinterpret_cast<__nv_bfloat162*>(g_xs + (size_t)row * KP2 + t * 4);
        d[0] = h01; d[1] = h23;
        d += 512;  d[0] = h01; d[1] = h23;
        d += 512;  d[0] = l01; d[1] = l23;
    } else {
        __nv_bfloat162* d = reinterpret_cast<__nv_bfloat162*>(g_ws + (size_t)row * KP2 + t * 4);
        d[0] = h01; d[1] = h23;
        d += 512;  d[0] = l01; d[1] = l23;
        d += 512;  d[0] = h01; d[1] = h23;
    }
}

// ---------------------------------------------------------------------------
// GEMM1 via mma.sync: z_e = x @ W^T with packed 3-split (K''=3072).
// 128-thread CTAs, M-tile 64, 2 CTAs/SM. BLK_K=64, 3-stage cp.async.
// grid (4, 256). Epilogue also emits bf16(z_e).
// ---------------------------------------------------------------------------
#define G1_SA   8192                 // A stage bytes (64 x 128B)
#define G1_SB   16384                // B stage bytes (128 x 128B)
#define G1_BOFF (3 * G1_SA)          // 24576
#define SM1TOT  (3 * G1_SA + 3 * G1_SB)   // 73728 per CTA

__global__ __launch_bounds__(128, 2) void gemm1_mma_kernel() {
    extern __shared__ char sm[];
    const uint32_t sbase = smem_u32(sm);
    const int tid  = threadIdx.x;
    const int lane = tid & 31;
    const int warp_n = tid >> 5;       // 0..3
    const int row0 = blockIdx.y * 64;
    const int col0 = blockIdx.x * 128;
    const int NKIT = KP2 / 64;         // 48

    const __nv_bfloat16* gA = g_xs + (size_t)row0 * KP2;
    const __nv_bfloat16* gB = g_ws + (size_t)col0 * KP2;

    float acc[4][4][4];
    #pragma unroll
    for (int mf = 0; mf < 4; mf++)
        #pragma unroll
        for (int nf = 0; nf < 4; nf++)
            #pragma unroll
            for (int q = 0; q < 4; q++) acc[mf][nf][q] = 0.f;

    #define G1_ISSUE(stg, kit) do {                                               \
        const uint32_t As_ = sbase + (stg) * G1_SA;                               \
        const uint32_t Bs_ = sbase + G1_BOFF + (stg) * G1_SB;                     \
        const int koff_ = (kit) * 64;                                             \
        _Pragma("unroll")                                                          \
        for (int i_ = 0; i_ < 4; i_++) {                                           \
            int id_ = tid + i_ * 128;                                              \
            int r_  = id_ >> 3;                                                    \
            int c_  = id_ & 7;                                                     \
            cp_async16(As_ + SWB(r_, c_), gA + (size_t)r_ * KP2 + koff_ + c_ * 8); \
        }                                                                          \
        _Pragma("unroll")                                                          \
        for (int i_ = 0; i_ < 8; i_++) {                                           \
            int id_ = tid + i_ * 128;                                              \
            int r_  = id_ >> 3;                                                    \
            int c_  = id_ & 7;                                                     \
            cp_async16(Bs_ + SWB(r_, c_), gB + (size_t)r_ * KP2 + koff_ + c_ * 8); \
        }                                                                          \
    } while (0)

    G1_ISSUE(0, 0); cp_commit();
    G1_ISSUE(1, 1); cp_commit();

    const int g = lane >> 3;
    const int r8 = lane & 7;

    for (int kit = 0; kit < NKIT; kit++) {
        cp_wait1();
        __syncthreads();
        if (kit + 2 < NKIT) G1_ISSUE((kit + 2) % 3, kit + 2);
        cp_commit();

        const int stg = kit % 3;
        const uint32_t Abase = sbase + stg * G1_SA;
        const uint32_t Bbase = sbase + G1_BOFF + stg * G1_SB;

        #pragma unroll
        for (int ks = 0; ks < 4; ks++) {
            uint32_t afr[4][4];
            #pragma unroll
            for (int mf = 0; mf < 4; mf++) {
                int rr = mf * 16 + ((g & 1) << 3) + r8;
                int ch = 2 * ks + (g >> 1);
                ldsm_x4(afr[mf][0], afr[mf][1], afr[mf][2], afr[mf][3],
                        Abase + SWB(rr, ch));
            }
            uint32_t bfr[2][4];
            #pragma unroll
            for (int nf2 = 0; nf2 < 2; nf2++) {
                int rr = warp_n * 32 + nf2 * 16 + ((g >> 1) << 3) + r8;
                int ch = 2 * ks + (g & 1);
                ldsm_x4(bfr[nf2][0], bfr[nf2][1], bfr[nf2][2], bfr[nf2][3],
                        Bbase + SWB(rr, ch));
            }
            #pragma unroll
            for (int mf = 0; mf < 4; mf++)
                #pragma unroll
                for (int nf = 0; nf < 4; nf++)
                    mma_bf16(acc[mf][nf], afr[mf],
                             bfr[nf >> 1][(nf & 1) * 2], bfr[nf >> 1][(nf & 1) * 2 + 1]);
        }
    }
    #undef G1_ISSUE

    #pragma unroll
    for (int mf = 0; mf < 4; mf++)
        #pragma unroll
        for (int h = 0; h < 2; h++) {
            const int row = row0 + mf * 16 + h * 8 + (lane >> 2);
            #pragma unroll
            for (int nf = 0; nf < 4; nf++) {
                const int col = col0 + warp_n * 32 + nf * 8 + (lane & 3) * 2;
                float2 o; o.x = acc[mf][nf][h * 2]; o.y = acc[mf][nf][h * 2 + 1];
                *reinterpret_cast<float2*>(g_ze + (size_t)row * D_ + col) = o;
                __nv_bfloat162 hb;
                hb.x = __float2bfloat16_rn(o.x); hb.y = __float2bfloat16_rn(o.y);
                *reinterpret_cast<__nv_bfloat162*>(g_zb + (size_t)row * D_ + col) = hb;
            }
        }
}

// ---------------------------------------------------------------------------
// Phase 1: single-pass bf16 approx GEMM with packed sortable-uint top-2.
// Score key u = (bits(max(c2b - 2*dot, 0)) & 0xFFFFE000) | code  (positive
// fp32 bits are order-isomorphic to uints; index lives in low 13 bits).
// Top-2 update = 3 IMNMX. 128-thread CTAs, M-tile 64, 2 CTAs/SM.
// A resident (64KB), B streamed 16KB x 3. grid (8, 256).
// ---------------------------------------------------------------------------
#define P1_SM_A  0
#define P1_SM_B  65536
#define P1_SB    16384
#define P1_SMTOT (65536 + 3 * P1_SB)   // 114688 per CTA -> 2/SM

__global__ __launch_bounds__(128, 2) void phase1_kernel() {
    extern __shared__ char sm[];
    const uint32_t sbase = smem_u32(sm);
    const int tid  = threadIdx.x;
    const int lane = tid & 31;
    const int warp_n = tid >> 5;       // 0..3
    const int row0 = blockIdx.y * 64;
    const int code_base = blockIdx.x * 1024;

    // resident A: 64 rows x 64 chunks(16B)
    {
        const __nv_bfloat16* gA = g_zb + (size_t)row0 * D_;
        #pragma unroll
        for (int i = 0; i < 32; i++) {
            int idx = tid + i * 128;
            int r   = idx >> 6;
            int c16 = idx & 63;
            cp_async16(sbase + P1_SM_A + SWA(r, c16), gA + (size_t)r * D_ + c16 * 8);
        }
    }
    cp_commit();

    #define P1_ISSUE(stg, u) do {                                                  \
        const uint32_t Bs_ = sbase + P1_SM_B + (stg) * P1_SB;                      \
        const int nt_ = (u) >> 3, kit_ = (u) & 7;                                  \
        const __nv_bfloat16* gB_ = g_cbb + (size_t)(code_base + nt_ * 128) * D_;   \
        _Pragma("unroll")                                                          \
        for (int i_ = 0; i_ < 8; i_++) {                                           \
            int id_ = tid + i_ * 128;                                              \
            int r_  = id_ >> 3;                                                    \
            int c_  = id_ & 7;                                                     \
            cp_async16(Bs_ + SWB(r_, c_),                                          \
                       gB_ + (size_t)r_ * D_ + kit_ * 64 + c_ * 8);                \
        }                                                                          \
    } while (0)

    P1_ISSUE(0, 0); cp_commit();
    P1_ISSUE(1, 1); cp_commit();

    const int g = lane >> 3;
    const int r8 = lane & 7;
    float acc[4][4][4];

    // per-owner packed top-2 (8 row-slots per thread)
    uint32_t tv1[8], tv2[8];
    #pragma unroll
    for (int i = 0; i < 8; i++) { tv1[i] = 0xFFFFFFFFu; tv2[i] = 0xFFFFFFFFu; }

    // u already packed; 3-op branchless top-2
    #define TOP2U(u, r) do {                                                       \
        const uint32_t mx_ = max(tv1[r], (u));                                     \
        tv1[r] = min(tv1[r], (u));                                                 \
        tv2[r] = min(tv2[r], mx_);                                                 \
    } while (0)

    for (int u = 0; u < 64; u++) {
        const int nt = u >> 3, kit = u & 7;
        cp_wait1();
        __syncthreads();
        if (u + 2 < 64) P1_ISSUE((u + 2) % 3, u + 2);
        cp_commit();

        if (kit == 0) {
            #pragma unroll
            for (int mf = 0; mf < 4; mf++)
                #pragma unroll
                for (int nf = 0; nf < 4; nf++)
                    #pragma unroll
                    for (int q = 0; q < 4; q++) acc[mf][nf][q] = 0.f;
        }

        const uint32_t Bbase = sbase + P1_SM_B + (u % 3) * P1_SB;
        #pragma unroll
        for (int ks = 0; ks < 4; ks++) {
            uint32_t afr[4][4];
            #pragma unroll
            for (int mf = 0; mf < 4; mf++) {
                int rr  = mf * 16 + ((g & 1) << 3) + r8;
                int c16 = kit * 8 + 2 * ks + (g >> 1);
                ldsm_x4(afr[mf][0], afr[mf][1], afr[mf][2], afr[mf][3],
                        sbase + P1_SM_A + SWA(rr, c16));
            }
            uint32_t bfr[2][4];
            #pragma unroll
            for (int nf2 = 0; nf2 < 2; nf2++) {
                int rr = warp_n * 32 + nf2 * 16 + ((g >> 1) << 3) + r8;
                int ch = 2 * ks + (g & 1);
                ldsm_x4(bfr[nf2][0], bfr[nf2][1], bfr[nf2][2], bfr[nf2][3],
                        Bbase + SWB(rr, ch));
            }
            #pragma unroll
            for (int mf = 0; mf < 4; mf++)
                #pragma unroll
                for (int nf = 0; nf < 4; nf++)
                    mma_bf16(acc[mf][nf], afr[mf],
                             bfr[nf >> 1][(nf & 1) * 2], bfr[nf >> 1][(nf & 1) * 2 + 1]);
        }

        if (kit == 7) {   // tile done: pack + fold into top-2 (all branchless)
            #pragma unroll
            for (int nf = 0; nf < 4; nf++) {
                const int code0 = code_base + nt * 128 + warp_n * 32 + nf * 8 + (lane & 3) * 2;
                const float c2a = __ldg(&g_c2b[code0]);
                const float c2b = __ldg(&g_c2b[code0 + 1]);
                #pragma unroll
                for (int mf = 0; mf < 4; mf++)
                    #pragma unroll
                    for (int h = 0; h < 2; h++) {
                        const int ridx = mf * 2 + h;
                        float v0 = fmaxf(fmaf(-2.0f, acc[mf][nf][h * 2 + 0], c2a), 0.0f);
                        float v1 = fmaxf(fmaf(-2.0f, acc[mf][nf][h * 2 + 1], c2b), 0.0f);
                        uint32_t u0 = (__float_as_uint(v0) & 0xFFFFE000u) | (uint32_t)code0;
                        uint32_t u1 = (__float_as_uint(v1) & 0xFFFFE000u) | (uint32_t)(code0 + 1);
                        TOP2U(u0, ridx);
                        TOP2U(u1, ridx);
                    }
            }
        }
    }
    #undef P1_ISSUE
    #undef TOP2U

    // store per-owner packed top-2: one uint2 per (xblk,row,slot)
    const int slot = warp_n * 4 + (lane & 3);
    #pragma unroll
    for (int ridx = 0; ridx < 8; ridx++) {
        const int mf = ridx >> 1, h = ridx & 1;
        const int row = row0 + mf * 16 + h * 8 + (lane >> 2);
        uint2 v; v.x = tv1[ridx]; v.y = tv2[ridx];
        g_top[((size_t)blockIdx.x * B_ + row) * 16 + slot] = v;
    }
}

// ---------------------------------------------------------------------------
// Phase 2 (fused with zz + output): read 128 packed owners/row, gmin via
// umin (positive-float bit order), candidates = keys < bits(gmin_f+margin),
// index = key & 0x1FFF; ze row cached in registers; exact fp64 rescore
// (reference-grid fp32 rounding + lowest-index tie-break); writes z_q_st
// row, index, vq_loss. 1 warp per row.
// ---------------------------------------------------------------------------
__global__ __launch_bounds__(256) void phase2_kernel(const float* __restrict__ cb,
                                                     float* __restrict__ out) {
    __shared__ int s_cnt[8];
    __shared__ int s_list[8][CAP];
    const int wid  = threadIdx.x >> 5;
    const int lane = threadIdx.x & 31;
    const int row  = blockIdx.x * 8 + wid;

    // cache ze row in registers + fp64 zz (same reduction order as before)
    const float* ze = g_ze + (size_t)row * D_;
    float er[16];
    double zs = 0.0;
    #pragma unroll
    for (int j = 0; j < 16; j++) {
        er[j] = ze[lane + j * 32];
        double v = (double)er[j];
        zs += v * v;
    }
    #pragma unroll
    for (int o = 16; o; o >>= 1) zs += __shfl_xor_sync(0xffffffffu, zs, o);
    const float zz = (float)zs;

    uint2 own[4];
    uint32_t gmin = 0xFFFFFFFFu;
    #pragma unroll
    for (int j = 0; j < 4; j++) {
        const int o = lane * 4 + j;
        const int xblk = o >> 4, slot = o & 15;
        own[j] = g_top[((size_t)xblk * B_ + row) * 16 + slot];
        gmin = min(gmin, own[j].x);
    }
    #pragma unroll
    for (int o = 16; o; o >>= 1)
        gmin = min(gmin, (uint32_t)__shfl_xor_sync(0xffffffffu, gmin, o));
    const uint32_t thr = __float_as_uint(__uint_as_float(gmin) + MARGIN2);

    if (lane == 0) s_cnt[wid] = 0;
    __syncwarp();
    #pragma unroll
    for (int j = 0; j < 4; j++) {
        if (own[j].x < thr) {
            int p = atomicAdd(&s_cnt[wid], 1);
            if (p < CAP) s_list[wid][p] = (int)(own[j].x & 0x1FFFu);
        }
        if (own[j].y < thr) {
            int p = atomicAdd(&s_cnt[wid], 1);
            if (p < CAP) s_list[wid][p] = (int)(own[j].y & 0x1FFFu);
        }
    }
    __syncwarp();
    const int ncand = s_cnt[wid];

    float bv = 3.4e38f;
    int   bi = 0x7fffffff;

    if (ncand <= CAP) {
        for (int c = 0; c < ncand; c++) {
            const int k = s_list[wid][c];
            const float* cr = cb + (size_t)k * D_;
            double d = 0.0;
            #pragma unroll
            for (int j = 0; j < 16; j++)
                d = fma((double)er[j], (double)cr[lane + j * 32], d);
            #pragma unroll
            for (int o = 16; o; o >>= 1) d += __shfl_xor_sync(0xffffffffu, d, o);
            float t = __fadd_rn(zz, -2.0f * (float)d);
            float v = __fadd_rn(t, g_c2[k]);
            if (v < bv || (v == bv && k < bi)) { bv = v; bi = k; }
        }
    } else {
        // pathological fallback: full exact scan
        for (int k = 0; k < K_; k++) {
            const float* cr = cb + (size_t)k * D_;
            double d = 0.0;
            #pragma unroll
            for (int j = 0; j < 16; j++)
                d = fma((double)er[j], (double)cr[lane + j * 32], d);
            #pragma unroll
            for (int o = 16; o; o >>= 1) d += __shfl_xor_sync(0xffffffffu, d, o);
            float t = __fadd_rn(zz, -2.0f * (float)d);
            float v = __fadd_rn(t, g_c2[k]);
            if (v < bv || (v == bv && k < bi)) { bv = v; bi = k; }
        }
    }
    bi = __shfl_sync(0xffffffffu, bi, 0);

    // fused output: z_q_st row + loss + index (ze from registers)
    const float* zq = cb + (size_t)bi * D_;
    float* o = out + (size_t)row * D_;
    float s = 0.f;
    #pragma unroll
    for (int j = 0; j < 16; j++) {
        const int d = lane + j * 32;
        float e    = er[j];
        float q    = zq[d];
        float diff = q - e;
        o[d] = e + diff;
        s += diff * diff;
    }
    #pragma unroll
    for (int off = 16; off; off >>= 1) s += __shfl_xor_sync(0xffffffffu, s, off);
    if (lane == 0) {
        g_idx[row] = bi;
        out[(size_t)B_ * D_ + row]      = (float)bi;
        out[(size_t)B_ * D_ + B_ + row] = s / (float)D_;
    }
}

// ---------------------------------------------------------------------------
extern "C" void kernel_launch(void* const* d_in, const int* in_sizes, int n_in,
                              void* d_out, int out_size) {
    const float* x  = (const float*)d_in[0];
    const float* W  = (const float*)d_in[1];
    const float* cb = (const float*)d_in[2];
    float* out = (float*)d_out;
    (void)in_sizes; (void)n_in; (void)out_size;

    cudaFuncSetAttribute(gemm1_mma_kernel, cudaFuncAttributeMaxDynamicSharedMemorySize, SM1TOT);
    cudaFuncSetAttribute(phase1_kernel,    cudaFuncAttributeMaxDynamicSharedMemorySize, P1_SMTOT);

    pack_xw_kernel<<<B_ + D_, 256>>>(x, W);
    cbprep_kernel<<<K_ / 8, 256>>>(cb);
    gemm1_mma_kernel<<<dim3(4, 256), 128, SM1TOT>>>();
    phase1_kernel<<<dim3(8, 256), 128, P1_SMTOT>>>();
    phase2_kernel<<<B_ / 8, 256>>>(cb, out);
}

// round 14
// speedup vs baseline: 1.3856x; 1.0311x over previous
#include <cuda_runtime.h>
#include <cuda_bf16.h>
#include <cuda_fp16.h>
#include <cstdint>

// Problem constants
#define B_   16384
#define DIN  1024
#define D_   512
#define K_   8192
#define KP2  3072          // gemm1 packed K: [a0|a0|a1] . [b0|b1|b0]

#define MARGIN2 0.12f      // bf16 noise (0.08) + packed-score quantization slack
#define CAP     32

// ---------------------------------------------------------------------------
// Scratch (device globals; allocations forbidden)
// ---------------------------------------------------------------------------
__device__ float  g_ze[(size_t)B_ * D_];     // z_e fp32
__device__ float  g_c2[K_];                  // |c|^2 (exact, for rescore)
__device__ float  g_c2b[K_];                 // |c|^2 + 16 (biased, for phase1)
__device__ int    g_idx[B_];
__device__ uint2  g_top[(size_t)8 * B_ * 16];      // per-(xblk,row,slot) packed top-2, 16MB
__device__ __nv_bfloat16 g_xs[(size_t)B_ * KP2];   // packed x splits
__device__ __nv_bfloat16 g_ws[(size_t)D_ * KP2];   // packed W splits
__device__ __nv_bfloat16 g_zb[(size_t)B_ * D_];    // bf16(z_e)
__device__ __nv_bfloat16 g_cbb[(size_t)K_ * D_];   // bf16(cb)

// ---------------------------------------------------------------------------
// PTX helpers (baseline PTX only: works at .target sm_100)
// ---------------------------------------------------------------------------
__device__ __forceinline__ uint32_t smem_u32(const void* p) {
    uint32_t a;
    asm("{ .reg .u64 t; cvta.to.shared.u64 t, %1; cvt.u32.u64 %0, t; }" : "=r"(a) : "l"(p));
    return a;
}
__device__ __forceinline__ void cp_async16(uint32_t saddr, const void* gaddr) {
    asm volatile("cp.async.cg.shared.global [%0], [%1], 16;" :: "r"(saddr), "l"(gaddr));
}
__device__ __forceinline__ void cp_commit() { asm volatile("cp.async.commit_group;"); }
__device__ __forceinline__ void cp_wait1()  { asm volatile("cp.async.wait_group 1;" ::: "memory"); }

__device__ __forceinline__ void ldsm_x4(uint32_t& r0, uint32_t& r1, uint32_t& r2, uint32_t& r3,
                                        uint32_t addr) {
    asm volatile("ldmatrix.sync.aligned.m8n8.x4.shared.b16 {%0,%1,%2,%3}, [%4];"
                 : "=r"(r0), "=r"(r1), "=r"(r2), "=r"(r3) : "r"(addr));
}
__device__ __forceinline__ void mma_bf16(float* c, const uint32_t* a, uint32_t b0, uint32_t b1) {
    asm volatile("mma.sync.aligned.m16n8k16.row.col.f32.bf16.bf16.f32 "
                 "{%0,%1,%2,%3}, {%4,%5,%6,%7}, {%8,%9}, {%0,%1,%2,%3};"
                 : "+f"(c[0]), "+f"(c[1]), "+f"(c[2]), "+f"(c[3])
                 : "r"(a[0]), "r"(a[1]), "r"(a[2]), "r"(a[3]), "r"(b0), "r"(b1));
}

// Swizzles:
// A-resident (phase1): 1024B rows, 64 x 16B chunks, XOR within 8-chunk groups
#define SWA(r, c) ((r) * 1024 + ((((c) & 0x38) | (((c) & 7) ^ ((r) & 7))) << 4))
// 128B-row stage tiles (BLK_K=64 bf16): 8 x 16B chunks, XOR by row
#define SWB(r, c) ((r) * 128 + ((((c) ^ ((r) & 7)) & 7) << 4))

// ---------------------------------------------------------------------------
// Merged prep kernel (one launch):
//   blocks [0, B_)            : pack x row  -> g_xs  [a0|a0|a1]
//   blocks [B_, B_+D_)        : pack W row  -> g_ws  [b0|b1|b0]
//   blocks [B_+D_, +K_/8)     : codebook c2/c2b + bf16 pack (8 rows/block)
// ---------------------------------------------------------------------------
__global__ void prep_kernel(const float* __restrict__ x, const float* __restrict__ w,
                            const float* __restrict__ cb) {
    const int b = blockIdx.x, t = threadIdx.x;

    if (b < B_ + D_) {
        const bool isx = (b < B_);
        const int row = isx ? b : (b - B_);
        const float* src = isx ? x : w;

        float4 v = *reinterpret_cast<const float4*>(src + (size_t)row * DIN + t * 4);
        __nv_bfloat162 h01, h23, l01, l23;
        h01.x = __float2bfloat16_rn(v.x); h01.y = __float2bfloat16_rn(v.y);
        h23.x = __float2bfloat16_rn(v.z); h23.y = __float2bfloat16_rn(v.w);
        l01.x = __float2bfloat16_rn(v.x - __bfloat162float(h01.x));
        l01.y = __float2bfloat16_rn(v.y - __bfloat162float(h01.y));
        l23.x = __float2bfloat16_rn(v.z - __bfloat162float(h23.x));
        l23.y = __float2bfloat16_rn(v.w - __bfloat162float(h23.y));

        if (isx) {
            __nv_bfloat162* d = reinterpret_cast<__nv_bfloat162*>(g_xs + (size_t)row * KP2 + t * 4);
            d[0] = h01; d[1] = h23;
            d += 512;  d[0] = h01; d[1] = h23;
            d += 512;  d[0] = l01; d[1] = l23;
        } else {
            __nv_bfloat162* d = reinterpret_cast<__nv_bfloat162*>(g_ws + (size_t)row * KP2 + t * 4);
            d[0] = h01; d[1] = h23;
            d += 512;  d[0] = l01; d[1] = l23;
            d += 512;  d[0] = h01; d[1] = h23;
        }
    } else {
        const int row  = (b - B_ - D_) * 8 + (t >> 5);
        const int lane = t & 31;
        const float4* src = reinterpret_cast<const float4*>(cb + (size_t)row * D_);
        __nv_bfloat162* dst = reinterpret_cast<__nv_bfloat162*>(g_cbb + (size_t)row * D_);
        float s = 0.f;
        #pragma unroll
        for (int j = 0; j < 4; j++) {
            const int i = lane + j * 32;
            float4 v = src[i];
            s += v.x * v.x + v.y * v.y + v.z * v.z + v.w * v.w;
            __nv_bfloat162 h0, h1;
            h0.x = __float2bfloat16_rn(v.x); h0.y = __float2bfloat16_rn(v.y);
            h1.x = __float2bfloat16_rn(v.z); h1.y = __float2bfloat16_rn(v.w);
            dst[i * 2]     = h0;
            dst[i * 2 + 1] = h1;
        }
        #pragma unroll
        for (int o = 16; o; o >>= 1) s += __shfl_xor_sync(0xffffffffu, s, o);
        if (lane == 0) { g_c2[row] = s; g_c2b[row] = s + 16.0f; }
    }
}

// ---------------------------------------------------------------------------
// GEMM1 via mma.sync: z_e = x @ W^T with packed 3-split (K''=3072).
// 128-thread CTAs, M-tile 64, 3 CTAs/SM (72KB smem/CTA). BLK_K=64, 3-stage.
// grid (4, 256). Epilogue also emits bf16(z_e).
// ---------------------------------------------------------------------------
#define G1_SA   8192                 // A stage bytes (64 x 128B)
#define G1_SB   16384                // B stage bytes (128 x 128B)
#define G1_BOFF (3 * G1_SA)          // 24576
#define SM1TOT  (3 * G1_SA + 3 * G1_SB)   // 73728 per CTA -> 3/SM

__global__ __launch_bounds__(128, 3) void gemm1_mma_kernel() {
    extern __shared__ char sm[];
    const uint32_t sbase = smem_u32(sm);
    const int tid  = threadIdx.x;
    const int lane = tid & 31;
    const int warp_n = tid >> 5;       // 0..3
    const int row0 = blockIdx.y * 64;
    const int col0 = blockIdx.x * 128;
    const int NKIT = KP2 / 64;         // 48

    const __nv_bfloat16* gA = g_xs + (size_t)row0 * KP2;
    const __nv_bfloat16* gB = g_ws + (size_t)col0 * KP2;

    float acc[4][4][4];
    #pragma unroll
    for (int mf = 0; mf < 4; mf++)
        #pragma unroll
        for (int nf = 0; nf < 4; nf++)
            #pragma unroll
            for (int q = 0; q < 4; q++) acc[mf][nf][q] = 0.f;

    #define G1_ISSUE(stg, kit) do {                                               \
        const uint32_t As_ = sbase + (stg) * G1_SA;                               \
        const uint32_t Bs_ = sbase + G1_BOFF + (stg) * G1_SB;                     \
        const int koff_ = (kit) * 64;                                             \
        _Pragma("unroll")                                                          \
        for (int i_ = 0; i_ < 4; i_++) {                                           \
            int id_ = tid + i_ * 128;                                              \
            int r_  = id_ >> 3;                                                    \
            int c_  = id_ & 7;                                                     \
            cp_async16(As_ + SWB(r_, c_), gA + (size_t)r_ * KP2 + koff_ + c_ * 8); \
        }                                                                          \
        _Pragma("unroll")                                                          \
        for (int i_ = 0; i_ < 8; i_++) {                                           \
            int id_ = tid + i_ * 128;                                              \
            int r_  = id_ >> 3;                                                    \
            int c_  = id_ & 7;                                                     \
            cp_async16(Bs_ + SWB(r_, c_), gB + (size_t)r_ * KP2 + koff_ + c_ * 8); \
        }                                                                          \
    } while (0)

    G1_ISSUE(0, 0); cp_commit();
    G1_ISSUE(1, 1); cp_commit();

    const int g = lane >> 3;
    const int r8 = lane & 7;

    for (int kit = 0; kit < NKIT; kit++) {
        cp_wait1();
        __syncthreads();
        if (kit + 2 < NKIT) G1_ISSUE((kit + 2) % 3, kit + 2);
        cp_commit();

        const int stg = kit % 3;
        const uint32_t Abase = sbase + stg * G1_SA;
        const uint32_t Bbase = sbase + G1_BOFF + stg * G1_SB;

        #pragma unroll
        for (int ks = 0; ks < 4; ks++) {
            uint32_t afr[4][4];
            #pragma unroll
            for (int mf = 0; mf < 4; mf++) {
                int rr = mf * 16 + ((g & 1) << 3) + r8;
                int ch = 2 * ks + (g >> 1);
                ldsm_x4(afr[mf][0], afr[mf][1], afr[mf][2], afr[mf][3],
                        Abase + SWB(rr, ch));
            }
            uint32_t bfr[2][4];
            #pragma unroll
            for (int nf2 = 0; nf2 < 2; nf2++) {
                int rr = warp_n * 32 + nf2 * 16 + ((g >> 1) << 3) + r8;
                int ch = 2 * ks + (g & 1);
                ldsm_x4(bfr[nf2][0], bfr[nf2][1], bfr[nf2][2], bfr[nf2][3],
                        Bbase + SWB(rr, ch));
            }
            #pragma unroll
            for (int mf = 0; mf < 4; mf++)
                #pragma unroll
                for (int nf = 0; nf < 4; nf++)
                    mma_bf16(acc[mf][nf], afr[mf],
                             bfr[nf >> 1][(nf & 1) * 2], bfr[nf >> 1][(nf & 1) * 2 + 1]);
        }
    }
    #undef G1_ISSUE

    #pragma unroll
    for (int mf = 0; mf < 4; mf++)
        #pragma unroll
        for (int h = 0; h < 2; h++) {
            const int row = row0 + mf * 16 + h * 8 + (lane >> 2);
            #pragma unroll
            for (int nf = 0; nf < 4; nf++) {
                const int col = col0 + warp_n * 32 + nf * 8 + (lane & 3) * 2;
                float2 o; o.x = acc[mf][nf][h * 2]; o.y = acc[mf][nf][h * 2 + 1];
                *reinterpret_cast<float2*>(g_ze + (size_t)row * D_ + col) = o;
                __nv_bfloat162 hb;
                hb.x = __float2bfloat16_rn(o.x); hb.y = __float2bfloat16_rn(o.y);
                *reinterpret_cast<__nv_bfloat162*>(g_zb + (size_t)row * D_ + col) = hb;
            }
        }
}

// ---------------------------------------------------------------------------
// Phase 1: single-pass bf16 approx GEMM with packed sortable-uint top-2.
// Score key u = (bits(max(c2b - 2*dot, 0)) & 0xFFFFE000) | code. Top-2
// update = 3 IMNMX. 128-thread CTAs, M-tile 64, 2 CTAs/SM. A resident
// (64KB), B streamed 16KB x 3. grid (8, 256). UNCHANGED from round 13.
// ---------------------------------------------------------------------------
#define P1_SM_A  0
#define P1_SM_B  65536
#define P1_SB    16384
#define P1_SMTOT (65536 + 3 * P1_SB)   // 114688 per CTA -> 2/SM

__global__ __launch_bounds__(128, 2) void phase1_kernel() {
    extern __shared__ char sm[];
    const uint32_t sbase = smem_u32(sm);
    const int tid  = threadIdx.x;
    const int lane = tid & 31;
    const int warp_n = tid >> 5;       // 0..3
    const int row0 = blockIdx.y * 64;
    const int code_base = blockIdx.x * 1024;

    // resident A: 64 rows x 64 chunks(16B)
    {
        const __nv_bfloat16* gA = g_zb + (size_t)row0 * D_;
        #pragma unroll
        for (int i = 0; i < 32; i++) {
            int idx = tid + i * 128;
            int r   = idx >> 6;
            int c16 = idx & 63;
            cp_async16(sbase + P1_SM_A + SWA(r, c16), gA + (size_t)r * D_ + c16 * 8);
        }
    }
    cp_commit();

    #define P1_ISSUE(stg, u) do {                                                  \
        const uint32_t Bs_ = sbase + P1_SM_B + (stg) * P1_SB;                      \
        const int nt_ = (u) >> 3, kit_ = (u) & 7;                                  \
        const __nv_bfloat16* gB_ = g_cbb + (size_t)(code_base + nt_ * 128) * D_;   \
        _Pragma("unroll")                                                          \
        for (int i_ = 0; i_ < 8; i_++) {                                           \
            int id_ = tid + i_ * 128;                                              \
            int r_  = id_ >> 3;                                                    \
            int c_  = id_ & 7;                                                     \
            cp_async16(Bs_ + SWB(r_, c_),                                          \
                       gB_ + (size_t)r_ * D_ + kit_ * 64 + c_ * 8);                \
        }                                                                          \
    } while (0)

    P1_ISSUE(0, 0); cp_commit();
    P1_ISSUE(1, 1); cp_commit();

    const int g = lane >> 3;
    const int r8 = lane & 7;
    float acc[4][4][4];

    uint32_t tv1[8], tv2[8];
    #pragma unroll
    for (int i = 0; i < 8; i++) { tv1[i] = 0xFFFFFFFFu; tv2[i] = 0xFFFFFFFFu; }

    #define TOP2U(u, r) do {                                                       \
        const uint32_t mx_ = max(tv1[r], (u));                                     \
        tv1[r] = min(tv1[r], (u));                                                 \
        tv2[r] = min(tv2[r], mx_);                                                 \
    } while (0)

    for (int u = 0; u < 64; u++) {
        const int nt = u >> 3, kit = u & 7;
        cp_wait1();
        __syncthreads();
        if (u + 2 < 64) P1_ISSUE((u + 2) % 3, u + 2);
        cp_commit();

        if (kit == 0) {
            #pragma unroll
            for (int mf = 0; mf < 4; mf++)
                #pragma unroll
                for (int nf = 0; nf < 4; nf++)
                    #pragma unroll
                    for (int q = 0; q < 4; q++) acc[mf][nf][q] = 0.f;
        }

        const uint32_t Bbase = sbase + P1_SM_B + (u % 3) * P1_SB;
        #pragma unroll
        for (int ks = 0; ks < 4; ks++) {
            uint32_t afr[4][4];
            #pragma unroll
            for (int mf = 0; mf < 4; mf++) {
                int rr  = mf * 16 + ((g & 1) << 3) + r8;
                int c16 = kit * 8 + 2 * ks + (g >> 1);
                ldsm_x4(afr[mf][0], afr[mf][1], afr[mf][2], afr[mf][3],
                        sbase + P1_SM_A + SWA(rr, c16));
            }
            uint32_t bfr[2][4];
            #pragma unroll
            for (int nf2 = 0; nf2 < 2; nf2++) {
                int rr = warp_n * 32 + nf2 * 16 + ((g >> 1) << 3) + r8;
                int ch = 2 * ks + (g & 1);
                ldsm_x4(bfr[nf2][0], bfr[nf2][1], bfr[nf2][2], bfr[nf2][3],
                        Bbase + SWB(rr, ch));
            }
            #pragma unroll
            for (int mf = 0; mf < 4; mf++)
                #pragma unroll
                for (int nf = 0; nf < 4; nf++)
                    mma_bf16(acc[mf][nf], afr[mf],
                             bfr[nf >> 1][(nf & 1) * 2], bfr[nf >> 1][(nf & 1) * 2 + 1]);
        }

        if (kit == 7) {   // tile done: pack + fold into top-2 (all branchless)
            #pragma unroll
            for (int nf = 0; nf < 4; nf++) {
                const int code0 = code_base + nt * 128 + warp_n * 32 + nf * 8 + (lane & 3) * 2;
                const float c2a = __ldg(&g_c2b[code0]);
                const float c2b = __ldg(&g_c2b[code0 + 1]);
                #pragma unroll
                for (int mf = 0; mf < 4; mf++)
                    #pragma unroll
                    for (int h = 0; h < 2; h++) {
                        const int ridx = mf * 2 + h;
                        float v0 = fmaxf(fmaf(-2.0f, acc[mf][nf][h * 2 + 0], c2a), 0.0f);
                        float v1 = fmaxf(fmaf(-2.0f, acc[mf][nf][h * 2 + 1], c2b), 0.0f);
                        uint32_t u0 = (__float_as_uint(v0) & 0xFFFFE000u) | (uint32_t)code0;
                        uint32_t u1 = (__float_as_uint(v1) & 0xFFFFE000u) | (uint32_t)(code0 + 1);
                        TOP2U(u0, ridx);
                        TOP2U(u1, ridx);
                    }
            }
        }
    }
    #undef P1_ISSUE
    #undef TOP2U

    const int slot = warp_n * 4 + (lane & 3);
    #pragma unroll
    for (int ridx = 0; ridx < 8; ridx++) {
        const int mf = ridx >> 1, h = ridx & 1;
        const int row = row0 + mf * 16 + h * 8 + (lane >> 2);
        uint2 v; v.x = tv1[ridx]; v.y = tv2[ridx];
        g_top[((size_t)blockIdx.x * B_ + row) * 16 + slot] = v;
    }
}

// ---------------------------------------------------------------------------
// Phase 2 (fused zz + output): unchanged from round 13.
// ---------------------------------------------------------------------------
__global__ __launch_bounds__(256) void phase2_kernel(const float* __restrict__ cb,
                                                     float* __restrict__ out) {
    __shared__ int s_cnt[8];
    __shared__ int s_list[8][CAP];
    const int wid  = threadIdx.x >> 5;
    const int lane = threadIdx.x & 31;
    const int row  = blockIdx.x * 8 + wid;

    const float* ze = g_ze + (size_t)row * D_;
    float er[16];
    double zs = 0.0;
    #pragma unroll
    for (int j = 0; j < 16; j++) {
        er[j] = ze[lane + j * 32];
        double v = (double)er[j];
        zs += v * v;
    }
    #pragma unroll
    for (int o = 16; o; o >>= 1) zs += __shfl_xor_sync(0xffffffffu, zs, o);
    const float zz = (float)zs;

    uint2 own[4];
    uint32_t gmin = 0xFFFFFFFFu;
    #pragma unroll
    for (int j = 0; j < 4; j++) {
        const int o = lane * 4 + j;
        const int xblk = o >> 4, slot = o & 15;
        own[j] = g_top[((size_t)xblk * B_ + row) * 16 + slot];
        gmin = min(gmin, own[j].x);
    }
    #pragma unroll
    for (int o = 16; o; o >>= 1)
        gmin = min(gmin, (uint32_t)__shfl_xor_sync(0xffffffffu, gmin, o));
    const uint32_t thr = __float_as_uint(__uint_as_float(gmin) + MARGIN2);

    if (lane == 0) s_cnt[wid] = 0;
    __syncwarp();
    #pragma unroll
    for (int j = 0; j < 4; j++) {
        if (own[j].x < thr) {
            int p = atomicAdd(&s_cnt[wid], 1);
            if (p < CAP) s_list[wid][p] = (int)(own[j].x & 0x1FFFu);
        }
        if (own[j].y < thr) {
            int p = atomicAdd(&s_cnt[wid], 1);
            if (p < CAP) s_list[wid][p] = (int)(own[j].y & 0x1FFFu);
        }
    }
    __syncwarp();
    const int ncand = s_cnt[wid];

    float bv = 3.4e38f;
    int   bi = 0x7fffffff;

    if (ncand <= CAP) {
        for (int c = 0; c < ncand; c++) {
            const int k = s_list[wid][c];
            const float* cr = cb + (size_t)k * D_;
            double d = 0.0;
            #pragma unroll
            for (int j = 0; j < 16; j++)
                d = fma((double)er[j], (double)cr[lane + j * 32], d);
            #pragma unroll
            for (int o = 16; o; o >>= 1) d += __shfl_xor_sync(0xffffffffu, d, o);
            float t = __fadd_rn(zz, -2.0f * (float)d);
            float v = __fadd_rn(t, g_c2[k]);
            if (v < bv || (v == bv && k < bi)) { bv = v; bi = k; }
        }
    } else {
        for (int k = 0; k < K_; k++) {
            const float* cr = cb + (size_t)k * D_;
            double d = 0.0;
            #pragma unroll
            for (int j = 0; j < 16; j++)
                d = fma((double)er[j], (double)cr[lane + j * 32], d);
            #pragma unroll
            for (int o = 16; o; o >>= 1) d += __shfl_xor_sync(0xffffffffu, d, o);
            float t = __fadd_rn(zz, -2.0f * (float)d);
            float v = __fadd_rn(t, g_c2[k]);
            if (v < bv || (v == bv && k < bi)) { bv = v; bi = k; }
        }
    }
    bi = __shfl_sync(0xffffffffu, bi, 0);

    const float* zq = cb + (size_t)bi * D_;
    float* o = out + (size_t)row * D_;
    float s = 0.f;
    #pragma unroll
    for (int j = 0; j < 16; j++) {
        const int d = lane + j * 32;
        float e    = er[j];
        float q    = zq[d];
        float diff = q - e;
        o[d] = e + diff;
        s += diff * diff;
    }
    #pragma unroll
    for (int off = 16; off; off >>= 1) s += __shfl_xor_sync(0xffffffffu, s, off);
    if (lane == 0) {
        g_idx[row] = bi;
        out[(size_t)B_ * D_ + row]      = (float)bi;
        out[(size_t)B_ * D_ + B_ + row] = s / (float)D_;
    }
}

// ---------------------------------------------------------------------------
extern "C" void kernel_launch(void* const* d_in, const int* in_sizes, int n_in,
                              void* d_out, int out_size) {
    const float* x  = (const float*)d_in[0];
    const float* W  = (const float*)d_in[1];
    const float* cb = (const float*)d_in[2];
    float* out = (float*)d_out;
    (void)in_sizes; (void)n_in; (void)out_size;

    cudaFuncSetAttribute(gemm1_mma_kernel, cudaFuncAttributeMaxDynamicSharedMemorySize, SM1TOT);
    cudaFuncSetAttribute(phase1_kernel,    cudaFuncAttributeMaxDynamicSharedMemorySize, P1_SMTOT);

    prep_kernel<<<B_ + D_ + K_ / 8, 256>>>(x, W, cb);
    gemm1_mma_kernel<<<dim3(4, 256), 128, SM1TOT>>>();
    phase1_kernel<<<dim3(8, 256), 128, P1_SMTOT>>>();
    phase2_kernel<<<B_ / 8, 256>>>(cb, out);
}

// round 15
// speedup vs baseline: 1.3992x; 1.0098x over previous
#include <cuda_runtime.h>
#include <cuda_bf16.h>
#include <cuda_fp16.h>
#include <cstdint>

// Problem constants
#define B_   16384
#define DIN  1024
#define D_   512
#define K_   8192
#define KP2  3072          // gemm1 packed K: [a0|a0|a1] . [b0|b1|b0]

#define MARGIN2 0.16f      // bf16 noise (0.08) + packed-score quantization slack @ bias 48
#define CAP     32
#define BIAS    48.0f

// ---------------------------------------------------------------------------
// Scratch (device globals; allocations forbidden)
// ---------------------------------------------------------------------------
__device__ float  g_ze[(size_t)B_ * D_];     // z_e fp32
__device__ float  g_c2[K_];                  // |c|^2 (exact, for rescore)
__device__ float  g_c2b[K_];                 // |c|^2 + BIAS (for phase1 keys)
__device__ int    g_idx[B_];
__device__ uint2  g_top[(size_t)8 * B_ * 16];      // per-(xblk,row,slot) packed top-2, 16MB
__device__ __nv_bfloat16 g_xs[(size_t)B_ * KP2];   // packed x splits
__device__ __nv_bfloat16 g_ws[(size_t)D_ * KP2];   // packed W splits
__device__ __nv_bfloat16 g_zb[(size_t)B_ * D_];    // bf16(z_e)
__device__ __nv_bfloat16 g_cbb[(size_t)K_ * D_];   // bf16(cb)

// ---------------------------------------------------------------------------
// PTX helpers (baseline PTX only: works at .target sm_100)
// ---------------------------------------------------------------------------
__device__ __forceinline__ uint32_t smem_u32(const void* p) {
    uint32_t a;
    asm("{ .reg .u64 t; cvta.to.shared.u64 t, %1; cvt.u32.u64 %0, t; }" : "=r"(a) : "l"(p));
    return a;
}
__device__ __forceinline__ void cp_async16(uint32_t saddr, const void* gaddr) {
    asm volatile("cp.async.cg.shared.global [%0], [%1], 16;" :: "r"(saddr), "l"(gaddr));
}
__device__ __forceinline__ void cp_commit() { asm volatile("cp.async.commit_group;"); }
__device__ __forceinline__ void cp_wait1()  { asm volatile("cp.async.wait_group 1;" ::: "memory"); }

__device__ __forceinline__ void ldsm_x4(uint32_t& r0, uint32_t& r1, uint32_t& r2, uint32_t& r3,
                                        uint32_t addr) {
    asm volatile("ldmatrix.sync.aligned.m8n8.x4.shared.b16 {%0,%1,%2,%3}, [%4];"
                 : "=r"(r0), "=r"(r1), "=r"(r2), "=r"(r3) : "r"(addr));
}
__device__ __forceinline__ void mma_bf16(float* c, const uint32_t* a, uint32_t b0, uint32_t b1) {
    asm volatile("mma.sync.aligned.m16n8k16.row.col.f32.bf16.bf16.f32 "
                 "{%0,%1,%2,%3}, {%4,%5,%6,%7}, {%8,%9}, {%0,%1,%2,%3};"
                 : "+f"(c[0]), "+f"(c[1]), "+f"(c[2]), "+f"(c[3])
                 : "r"(a[0]), "r"(a[1]), "r"(a[2]), "r"(a[3]), "r"(b0), "r"(b1));
}

// Swizzles:
// A-resident (phase1): 1024B rows, 64 x 16B chunks, XOR within 8-chunk groups
#define SWA(r, c) ((r) * 1024 + ((((c) & 0x38) | (((c) & 7) ^ ((r) & 7))) << 4))
// 128B-row stage tiles (BLK_K=64 bf16): 8 x 16B chunks, XOR by row
#define SWB(r, c) ((r) * 128 + ((((c) ^ ((r) & 7)) & 7) << 4))

// ---------------------------------------------------------------------------
// Merged prep kernel (one launch):
//   blocks [0, B_)            : pack x row  -> g_xs  [a0|a0|a1]
//   blocks [B_, B_+D_)        : pack W row  -> g_ws  [b0|b1|b0]
//   blocks [B_+D_, +K_/8)     : codebook c2/c2b + bf16 pack (8 rows/block)
// ---------------------------------------------------------------------------
__global__ void prep_kernel(const float* __restrict__ x, const float* __restrict__ w,
                            const float* __restrict__ cb) {
    const int b = blockIdx.x, t = threadIdx.x;

    if (b < B_ + D_) {
        const bool isx = (b < B_);
        const int row = isx ? b : (b - B_);
        const float* src = isx ? x : w;

        float4 v = *reinterpret_cast<const float4*>(src + (size_t)row * DIN + t * 4);
        __nv_bfloat162 h01, h23, l01, l23;
        h01.x = __float2bfloat16_rn(v.x); h01.y = __float2bfloat16_rn(v.y);
        h23.x = __float2bfloat16_rn(v.z); h23.y = __float2bfloat16_rn(v.w);
        l01.x = __float2bfloat16_rn(v.x - __bfloat162float(h01.x));
        l01.y = __float2bfloat16_rn(v.y - __bfloat162float(h01.y));
        l23.x = __float2bfloat16_rn(v.z - __bfloat162float(h23.x));
        l23.y = __float2bfloat16_rn(v.w - __bfloat162float(h23.y));

        if (isx) {
            __nv_bfloat162* d = reinterpret_cast<__nv_bfloat162*>(g_xs + (size_t)row * KP2 + t * 4);
            d[0] = h01; d[1] = h23;
            d += 512;  d[0] = h01; d[1] = h23;
            d += 512;  d[0] = l01; d[1] = l23;
        } else {
            __nv_bfloat162* d = reinterpret_cast<__nv_bfloat162*>(g_ws + (size_t)row * KP2 + t * 4);
            d[0] = h01; d[1] = h23;
            d += 512;  d[0] = l01; d[1] = l23;
            d += 512;  d[0] = h01; d[1] = h23;
        }
    } else {
        const int row  = (b - B_ - D_) * 8 + (t >> 5);
        const int lane = t & 31;
        const float4* src = reinterpret_cast<const float4*>(cb + (size_t)row * D_);
        __nv_bfloat162* dst = reinterpret_cast<__nv_bfloat162*>(g_cbb + (size_t)row * D_);
        float s = 0.f;
        #pragma unroll
        for (int j = 0; j < 4; j++) {
            const int i = lane + j * 32;
            float4 v = src[i];
            s += v.x * v.x + v.y * v.y + v.z * v.z + v.w * v.w;
            __nv_bfloat162 h0, h1;
            h0.x = __float2bfloat16_rn(v.x); h0.y = __float2bfloat16_rn(v.y);
            h1.x = __float2bfloat16_rn(v.z); h1.y = __float2bfloat16_rn(v.w);
            dst[i * 2]     = h0;
            dst[i * 2 + 1] = h1;
        }
        #pragma unroll
        for (int o = 16; o; o >>= 1) s += __shfl_xor_sync(0xffffffffu, s, o);
        if (lane == 0) { g_c2[row] = s; g_c2b[row] = s + BIAS; }
    }
}

// ---------------------------------------------------------------------------
// GEMM1 via mma.sync: z_e = x @ W^T with packed 3-split (K''=3072).
// 128-thread CTAs, M-tile 64, 3 CTAs/SM (72KB smem/CTA). BLK_K=64, 3-stage.
// grid (4, 256). Epilogue also emits bf16(z_e). UNCHANGED (at ~78% roofline).
// ---------------------------------------------------------------------------
#define G1_SA   8192                 // A stage bytes (64 x 128B)
#define G1_SB   16384                // B stage bytes (128 x 128B)
#define G1_BOFF (3 * G1_SA)          // 24576
#define SM1TOT  (3 * G1_SA + 3 * G1_SB)   // 73728 per CTA -> 3/SM

__global__ __launch_bounds__(128, 3) void gemm1_mma_kernel() {
    extern __shared__ char sm[];
    const uint32_t sbase = smem_u32(sm);
    const int tid  = threadIdx.x;
    const int lane = tid & 31;
    const int warp_n = tid >> 5;       // 0..3
    const int row0 = blockIdx.y * 64;
    const int col0 = blockIdx.x * 128;
    const int NKIT = KP2 / 64;         // 48

    const __nv_bfloat16* gA = g_xs + (size_t)row0 * KP2;
    const __nv_bfloat16* gB = g_ws + (size_t)col0 * KP2;

    float acc[4][4][4];
    #pragma unroll
    for (int mf = 0; mf < 4; mf++)
        #pragma unroll
        for (int nf = 0; nf < 4; nf++)
            #pragma unroll
            for (int q = 0; q < 4; q++) acc[mf][nf][q] = 0.f;

    #define G1_ISSUE(stg, kit) do {                                               \
        const uint32_t As_ = sbase + (stg) * G1_SA;                               \
        const uint32_t Bs_ = sbase + G1_BOFF + (stg) * G1_SB;                     \
        const int koff_ = (kit) * 64;                                             \
        _Pragma("unroll")                                                          \
        for (int i_ = 0; i_ < 4; i_++) {                                           \
            int id_ = tid + i_ * 128;                                              \
            int r_  = id_ >> 3;                                                    \
            int c_  = id_ & 7;                                                     \
            cp_async16(As_ + SWB(r_, c_), gA + (size_t)r_ * KP2 + koff_ + c_ * 8); \
        }                                                                          \
        _Pragma("unroll")                                                          \
        for (int i_ = 0; i_ < 8; i_++) {                                           \
            int id_ = tid + i_ * 128;                                              \
            int r_  = id_ >> 3;                                                    \
            int c_  = id_ & 7;                                                     \
            cp_async16(Bs_ + SWB(r_, c_), gB + (size_t)r_ * KP2 + koff_ + c_ * 8); \
        }                                                                          \
    } while (0)

    G1_ISSUE(0, 0); cp_commit();
    G1_ISSUE(1, 1); cp_commit();

    const int g = lane >> 3;
    const int r8 = lane & 7;

    for (int kit = 0; kit < NKIT; kit++) {
        cp_wait1();
        __syncthreads();
        if (kit + 2 < NKIT) G1_ISSUE((kit + 2) % 3, kit + 2);
        cp_commit();

        const int stg = kit % 3;
        const uint32_t Abase = sbase + stg * G1_SA;
        const uint32_t Bbase = sbase + G1_BOFF + stg * G1_SB;

        #pragma unroll
        for (int ks = 0; ks < 4; ks++) {
            uint32_t afr[4][4];
            #pragma unroll
            for (int mf = 0; mf < 4; mf++) {
                int rr = mf * 16 + ((g & 1) << 3) + r8;
                int ch = 2 * ks + (g >> 1);
                ldsm_x4(afr[mf][0], afr[mf][1], afr[mf][2], afr[mf][3],
                        Abase + SWB(rr, ch));
            }
            uint32_t bfr[2][4];
            #pragma unroll
            for (int nf2 = 0; nf2 < 2; nf2++) {
                int rr = warp_n * 32 + nf2 * 16 + ((g >> 1) << 3) + r8;
                int ch = 2 * ks + (g & 1);
                ldsm_x4(bfr[nf2][0], bfr[nf2][1], bfr[nf2][2], bfr[nf2][3],
                        Bbase + SWB(rr, ch));
            }
            #pragma unroll
            for (int mf = 0; mf < 4; mf++)
                #pragma unroll
                for (int nf = 0; nf < 4; nf++)
                    mma_bf16(acc[mf][nf], afr[mf],
                             bfr[nf >> 1][(nf & 1) * 2], bfr[nf >> 1][(nf & 1) * 2 + 1]);
        }
    }
    #undef G1_ISSUE

    #pragma unroll
    for (int mf = 0; mf < 4; mf++)
        #pragma unroll
        for (int h = 0; h < 2; h++) {
            const int row = row0 + mf * 16 + h * 8 + (lane >> 2);
            #pragma unroll
            for (int nf = 0; nf < 4; nf++) {
                const int col = col0 + warp_n * 32 + nf * 8 + (lane & 3) * 2;
                float2 o; o.x = acc[mf][nf][h * 2]; o.y = acc[mf][nf][h * 2 + 1];
                *reinterpret_cast<float2*>(g_ze + (size_t)row * D_ + col) = o;
                __nv_bfloat162 hb;
                hb.x = __float2bfloat16_rn(o.x); hb.y = __float2bfloat16_rn(o.y);
                *reinterpret_cast<__nv_bfloat162*>(g_zb + (size_t)row * D_ + col) = hb;
            }
        }
}

// ---------------------------------------------------------------------------
// Phase 1: single-pass bf16 approx GEMM with packed sortable-uint top-2.
// Score key u = (bits(c2b - 2*dot) & 0xFFFFE000) | code; bias 48 keeps the
// value strictly positive (no clamp needed: score<0 requires a ~30-sigma
// bf16 dot error). Top-2 update = 3 IMNMX. 128-thread CTAs, M-tile 64,
// 2 CTAs/SM. A resident (64KB), B streamed 16KB x 3. grid (8, 256).
// ---------------------------------------------------------------------------
#define P1_SM_A  0
#define P1_SM_B  65536
#define P1_SB    16384
#define P1_SMTOT (65536 + 3 * P1_SB)   // 114688 per CTA -> 2/SM

__global__ __launch_bounds__(128, 2) void phase1_kernel() {
    extern __shared__ char sm[];
    const uint32_t sbase = smem_u32(sm);
    const int tid  = threadIdx.x;
    const int lane = tid & 31;
    const int warp_n = tid >> 5;       // 0..3
    const int row0 = blockIdx.y * 64;
    const int code_base = blockIdx.x * 1024;

    // resident A: 64 rows x 64 chunks(16B)
    {
        const __nv_bfloat16* gA = g_zb + (size_t)row0 * D_;
        #pragma unroll
        for (int i = 0; i < 32; i++) {
            int idx = tid + i * 128;
            int r   = idx >> 6;
            int c16 = idx & 63;
            cp_async16(sbase + P1_SM_A + SWA(r, c16), gA + (size_t)r * D_ + c16 * 8);
        }
    }
    cp_commit();

    #define P1_ISSUE(stg, u) do {                                                  \
        const uint32_t Bs_ = sbase + P1_SM_B + (stg) * P1_SB;                      \
        const int nt_ = (u) >> 3, kit_ = (u) & 7;                                  \
        const __nv_bfloat16* gB_ = g_cbb + (size_t)(code_base + nt_ * 128) * D_;   \
        _Pragma("unroll")                                                          \
        for (int i_ = 0; i_ < 8; i_++) {                                           \
            int id_ = tid + i_ * 128;                                              \
            int r_  = id_ >> 3;                                                    \
            int c_  = id_ & 7;                                                     \
            cp_async16(Bs_ + SWB(r_, c_),                                          \
                       gB_ + (size_t)r_ * D_ + kit_ * 64 + c_ * 8);                \
        }                                                                          \
    } while (0)

    P1_ISSUE(0, 0); cp_commit();
    P1_ISSUE(1, 1); cp_commit();

    const int g = lane >> 3;
    const int r8 = lane & 7;
    float acc[4][4][4];

    uint32_t tv1[8], tv2[8];
    #pragma unroll
    for (int i = 0; i < 8; i++) { tv1[i] = 0xFFFFFFFFu; tv2[i] = 0xFFFFFFFFu; }

    #define TOP2U(u, r) do {                                                       \
        const uint32_t mx_ = max(tv1[r], (u));                                     \
        tv1[r] = min(tv1[r], (u));                                                 \
        tv2[r] = min(tv2[r], mx_);                                                 \
    } while (0)

    for (int u = 0; u < 64; u++) {
        const int nt = u >> 3, kit = u & 7;
        cp_wait1();
        __syncthreads();
        if (u + 2 < 64) P1_ISSUE((u + 2) % 3, u + 2);
        cp_commit();

        if (kit == 0) {
            #pragma unroll
            for (int mf = 0; mf < 4; mf++)
                #pragma unroll
                for (int nf = 0; nf < 4; nf++)
                    #pragma unroll
                    for (int q = 0; q < 4; q++) acc[mf][nf][q] = 0.f;
        }

        const uint32_t Bbase = sbase + P1_SM_B + (u % 3) * P1_SB;
        #pragma unroll
        for (int ks = 0; ks < 4; ks++) {
            uint32_t afr[4][4];
            #pragma unroll
            for (int mf = 0; mf < 4; mf++) {
                int rr  = mf * 16 + ((g & 1) << 3) + r8;
                int c16 = kit * 8 + 2 * ks + (g >> 1);
                ldsm_x4(afr[mf][0], afr[mf][1], afr[mf][2], afr[mf][3],
                        sbase + P1_SM_A + SWA(rr, c16));
            }
            uint32_t bfr[2][4];
            #pragma unroll
            for (int nf2 = 0; nf2 < 2; nf2++) {
                int rr = warp_n * 32 + nf2 * 16 + ((g >> 1) << 3) + r8;
                int ch = 2 * ks + (g & 1);
                ldsm_x4(bfr[nf2][0], bfr[nf2][1], bfr[nf2][2], bfr[nf2][3],
                        Bbase + SWB(rr, ch));
            }
            #pragma unroll
            for (int mf = 0; mf < 4; mf++)
                #pragma unroll
                for (int nf = 0; nf < 4; nf++)
                    mma_bf16(acc[mf][nf], afr[mf],
                             bfr[nf >> 1][(nf & 1) * 2], bfr[nf >> 1][(nf & 1) * 2 + 1]);
        }

        if (kit == 7) {   // tile done: pack + fold into top-2 (all branchless)
            #pragma unroll
            for (int nf = 0; nf < 4; nf++) {
                const int code0 = code_base + nt * 128 + warp_n * 32 + nf * 8 + (lane & 3) * 2;
                const float2 c2p = __ldg(reinterpret_cast<const float2*>(&g_c2b[code0]));
                #pragma unroll
                for (int mf = 0; mf < 4; mf++)
                    #pragma unroll
                    for (int h = 0; h < 2; h++) {
                        const int ridx = mf * 2 + h;
                        float v0 = fmaf(-2.0f, acc[mf][nf][h * 2 + 0], c2p.x);
                        float v1 = fmaf(-2.0f, acc[mf][nf][h * 2 + 1], c2p.y);
                        uint32_t u0 = (__float_as_uint(v0) & 0xFFFFE000u) | (uint32_t)code0;
                        uint32_t u1 = (__float_as_uint(v1) & 0xFFFFE000u) | (uint32_t)(code0 + 1);
                        TOP2U(u0, ridx);
                        TOP2U(u1, ridx);
                    }
            }
        }
    }
    #undef P1_ISSUE
    #undef TOP2U

    const int slot = warp_n * 4 + (lane & 3);
    #pragma unroll
    for (int ridx = 0; ridx < 8; ridx++) {
        const int mf = ridx >> 1, h = ridx & 1;
        const int row = row0 + mf * 16 + h * 8 + (lane >> 2);
        uint2 v; v.x = tv1[ridx]; v.y = tv2[ridx];
        g_top[((size_t)blockIdx.x * B_ + row) * 16 + slot] = v;
    }
}

// ---------------------------------------------------------------------------
// Phase 2 (fused zz + output): read 128 packed owners/row, gmin via umin,
// candidates = keys < bits(gmin_f+margin), index = key & 0x1FFF; exact fp64
// rescore (reference-grid fp32 rounding + lowest-index tie-break); writes
// z_q_st row, index, vq_loss. 1 warp per row.
// ---------------------------------------------------------------------------
__global__ __launch_bounds__(256) void phase2_kernel(const float* __restrict__ cb,
                                                     float* __restrict__ out) {
    __shared__ int s_cnt[8];
    __shared__ int s_list[8][CAP];
    const int wid  = threadIdx.x >> 5;
    const int lane = threadIdx.x & 31;
    const int row  = blockIdx.x * 8 + wid;

    const float* ze = g_ze + (size_t)row * D_;
    float er[16];
    double zs = 0.0;
    #pragma unroll
    for (int j = 0; j < 16; j++) {
        er[j] = ze[lane + j * 32];
        double v = (double)er[j];
        zs += v * v;
    }
    #pragma unroll
    for (int o = 16; o; o >>= 1) zs += __shfl_xor_sync(0xffffffffu, zs, o);
    const float zz = (float)zs;

    uint2 own[4];
    uint32_t gmin = 0xFFFFFFFFu;
    #pragma unroll
    for (int j = 0; j < 4; j++) {
        const int o = lane * 4 + j;
        const int xblk = o >> 4, slot = o & 15;
        own[j] = g_top[((size_t)xblk * B_ + row) * 16 + slot];
        gmin = min(gmin, own[j].x);
    }
    #pragma unroll
    for (int o = 16; o; o >>= 1)
        gmin = min(gmin, (uint32_t)__shfl_xor_sync(0xffffffffu, gmin, o));
    const uint32_t thr = __float_as_uint(__uint_as_float(gmin) + MARGIN2);

    if (lane == 0) s_cnt[wid] = 0;
    __syncwarp();
    #pragma unroll
    for (int j = 0; j < 4; j++) {
        if (own[j].x < thr) {
            int p = atomicAdd(&s_cnt[wid], 1);
            if (p < CAP) s_list[wid][p] = (int)(own[j].x & 0x1FFFu);
        }
        if (own[j].y < thr) {
            int p = atomicAdd(&s_cnt[wid], 1);
            if (p < CAP) s_list[wid][p] = (int)(own[j].y & 0x1FFFu);
        }
    }
    __syncwarp();
    const int ncand = s_cnt[wid];

    float bv = 3.4e38f;
    int   bi = 0x7fffffff;

    if (ncand <= CAP) {
        for (int c = 0; c < ncand; c++) {
            const int k = s_list[wid][c];
            const float* cr = cb + (size_t)k * D_;
            double d = 0.0;
            #pragma unroll
            for (int j = 0; j < 16; j++)
                d = fma((double)er[j], (double)cr[lane + j * 32], d);
            #pragma unroll
            for (int o = 16; o; o >>= 1) d += __shfl_xor_sync(0xffffffffu, d, o);
            float t = __fadd_rn(zz, -2.0f * (float)d);
            float v = __fadd_rn(t, g_c2[k]);
            if (v < bv || (v == bv && k < bi)) { bv = v; bi = k; }
        }
    } else {
        for (int k = 0; k < K_; k++) {
            const float* cr = cb + (size_t)k * D_;
            double d = 0.0;
            #pragma unroll
            for (int j = 0; j < 16; j++)
                d = fma((double)er[j], (double)cr[lane + j * 32], d);
            #pragma unroll
            for (int o = 16; o; o >>= 1) d += __shfl_xor_sync(0xffffffffu, d, o);
            float t = __fadd_rn(zz, -2.0f * (float)d);
            float v = __fadd_rn(t, g_c2[k]);
            if (v < bv || (v == bv && k < bi)) { bv = v; bi = k; }
        }
    }
    bi = __shfl_sync(0xffffffffu, bi, 0);

    const float* zq = cb + (size_t)bi * D_;
    float* o = out + (size_t)row * D_;
    float s = 0.f;
    #pragma unroll
    for (int j = 0; j < 16; j++) {
        const int d = lane + j * 32;
        float e    = er[j];
        float q    = zq[d];
        float diff = q - e;
        o[d] = e + diff;
        s += diff * diff;
    }
    #pragma unroll
    for (int off = 16; off; off >>= 1) s += __shfl_xor_sync(0xffffffffu, s, off);
    if (lane == 0) {
        g_idx[row] = bi;
        out[(size_t)B_ * D_ + row]      = (float)bi;
        out[(size_t)B_ * D_ + B_ + row] = s / (float)D_;
    }
}

// ---------------------------------------------------------------------------
extern "C" void kernel_launch(void* const* d_in, const int* in_sizes, int n_in,
                              void* d_out, int out_size) {
    const float* x  = (const float*)d_in[0];
    const float* W  = (const float*)d_in[1];
    const float* cb = (const float*)d_in[2];
    float* out = (float*)d_out;
    (void)in_sizes; (void)n_in; (void)out_size;

    cudaFuncSetAttribute(gemm1_mma_kernel, cudaFuncAttributeMaxDynamicSharedMemorySize, SM1TOT);
    cudaFuncSetAttribute(phase1_kernel,    cudaFuncAttributeMaxDynamicSharedMemorySize, P1_SMTOT);

    prep_kernel<<<B_ + D_ + K_ / 8, 256>>>(x, W, cb);
    gemm1_mma_kernel<<<dim3(4, 256), 128, SM1TOT>>>();
    phase1_kernel<<<dim3(8, 256), 128, P1_SMTOT>>>();
    phase2_kernel<<<B_ / 8, 256>>>(cb, out);
}